// round 12
// baseline (speedup 1.0000x reference)
#include <cuda_runtime.h>
#include <cuda_fp16.h>
#include <math.h>
#include <stdint.h>

#define D_MODEL 1024
#define D_FFN   2048
#define N_TOK   4096
#define N_EXP   8
#define MAXSLOT 10240             /* 2*4096 + 8*256 padding */
#define NT_SH   (N_TOK / 256)     /* 16 shared row tiles (256 rows) */
#define NT_DN   (MAXSLOT / 256)   /* 40 expert row tiles */

#define A_TILE  20480             /* 256 rows * 80B */
#define B_TILE  10240             /* 128 rows * 80B */
#define STG_B   (A_TILE + B_TILE) /* 30720 */
#define MM_SMEM (3 * STG_B)       /* 92160, 3-stage ring */
#define GU_NSTG 32                /* K=1024 / 32 */
#define DN_NSTG 64                /* K=2048 / 32 */

// ---------------- scratch ----------------------------------------------------
__device__ __half g_Xh[(size_t)N_TOK * D_MODEL];
// gate+up interleaved: [slab][4096 n][1024 k]; n-chunk c (128 wide) = G cols
// [64c,64c+64) at +0..63, U cols [64c,64c+64) at +64..127
__device__ __half g_Bgu[(size_t)9 * 2 * D_FFN * D_MODEL];
__device__ __half g_Bd[(size_t)9 * D_MODEL * D_FFN];
__device__ __half g_Hs[(size_t)N_TOK * D_FFN];
__device__ __half g_He[(size_t)MAXSLOT * D_FFN];
__device__ float g_Os[(size_t)N_TOK * D_MODEL];
__device__ float g_Oe[(size_t)MAXSLOT * D_MODEL];
__device__ int   g_slot_token[MAXSLOT];
__device__ int   g_counts[N_EXP];
__device__ float g_psum[N_EXP];
__device__ int   g_fill[N_EXP];
__device__ int   g_padoff[N_EXP + 1];
__device__ int   g_tile_dn[NT_DN];
__device__ int   g_tok_idx[N_TOK * 2];
__device__ int   g_tok_slot[N_TOK * 2];
__device__ float g_tok_w[N_TOK * 2];

// ---------------- PTX helpers -------------------------------------------------
__device__ __forceinline__ uint32_t s2u(const void* p) {
    return (uint32_t)__cvta_generic_to_shared(p);
}
__device__ __forceinline__ void cpa16(uint32_t dst, const void* src) {
    asm volatile("cp.async.cg.shared.global [%0], [%1], 16;" :: "r"(dst), "l"(src));
}
__device__ __forceinline__ void cp_commit() {
    asm volatile("cp.async.commit_group;");
}
template <int N>
__device__ __forceinline__ void cp_wait() {
    asm volatile("cp.async.wait_group %0;" :: "n"(N));
}
__device__ __forceinline__ void ldm4(uint32_t* r, uint32_t addr) {
    asm volatile("ldmatrix.sync.aligned.m8n8.x4.shared.b16 {%0,%1,%2,%3}, [%4];"
                 : "=r"(r[0]), "=r"(r[1]), "=r"(r[2]), "=r"(r[3]) : "r"(addr));
}
__device__ __forceinline__ void mma_f16(float* c, const uint32_t* a,
                                        uint32_t b0, uint32_t b1) {
    asm volatile("mma.sync.aligned.m16n8k16.row.col.f32.f16.f16.f32 "
                 "{%0,%1,%2,%3}, {%4,%5,%6,%7}, {%8,%9}, {%0,%1,%2,%3};"
                 : "+f"(c[0]), "+f"(c[1]), "+f"(c[2]), "+f"(c[3])
                 : "r"(a[0]), "r"(a[1]), "r"(a[2]), "r"(a[3]), "r"(b0), "r"(b1));
}

// ---------------- routing kernels ---------------------------------------------
__global__ void init_kernel() {
    int i = blockIdx.x * blockDim.x + threadIdx.x;
    if (i < MAXSLOT) g_slot_token[i] = -1;
    if (i < N_EXP) { g_counts[i] = 0; g_psum[i] = 0.f; g_fill[i] = 0; }
}

__global__ void router_kernel(const float* __restrict__ x,
                              const float* __restrict__ rw) {
    int t = blockIdx.x * 4 + (threadIdx.x >> 5);
    int lane = threadIdx.x & 31;
    if (t >= N_TOK) return;
    const float* xr = x + (size_t)t * D_MODEL;
    float acc[N_EXP];
#pragma unroll
    for (int e = 0; e < N_EXP; e++) acc[e] = 0.f;
    for (int k = lane; k < D_MODEL; k += 32) {
        float xv = xr[k];
#pragma unroll
        for (int e = 0; e < N_EXP; e++) acc[e] += xv * rw[k * N_EXP + e];
    }
#pragma unroll
    for (int e = 0; e < N_EXP; e++)
#pragma unroll
        for (int o = 16; o; o >>= 1) acc[e] += __shfl_xor_sync(0xffffffffu, acc[e], o);
    if (lane == 0) {
        int i0 = 0; float v0 = acc[0];
#pragma unroll
        for (int e = 1; e < N_EXP; e++) if (acc[e] > v0) { v0 = acc[e]; i0 = e; }
        int i1 = -1; float v1 = -1e30f;
#pragma unroll
        for (int e = 0; e < N_EXP; e++) {
            if (e == i0) continue;
            if (acc[e] > v1) { v1 = acc[e]; i1 = e; }
        }
        float m2 = fmaxf(v0, v1);
        float e0 = expf(v0 - m2), e1 = expf(v1 - m2);
        float inv = 1.f / (e0 + e1);
        g_tok_idx[t * 2 + 0] = i0;  g_tok_w[t * 2 + 0] = e0 * inv;
        g_tok_idx[t * 2 + 1] = i1;  g_tok_w[t * 2 + 1] = e1 * inv;
        atomicAdd(&g_counts[i0], 1);
        atomicAdd(&g_counts[i1], 1);
        float mm = acc[0];
#pragma unroll
        for (int e = 1; e < N_EXP; e++) mm = fmaxf(mm, acc[e]);
        float s = 0.f, ex[N_EXP];
#pragma unroll
        for (int e = 0; e < N_EXP; e++) { ex[e] = expf(acc[e] - mm); s += ex[e]; }
        float invs = 1.f / s;
#pragma unroll
        for (int e = 0; e < N_EXP; e++) atomicAdd(&g_psum[e], ex[e] * invs);
    }
}

__global__ void offsets_kernel(float* __restrict__ out, int out_size) {
    __shared__ int spad[N_EXP + 1];
    int tid = threadIdx.x;
    if (tid == 0) {
        int off = 0;
        for (int e = 0; e < N_EXP; e++) {
            g_padoff[e] = off;
            off += ((g_counts[e] + 255) / 256) * 256;
        }
        g_padoff[N_EXP] = off;
        for (int e = 0; e <= N_EXP; e++) spad[e] = g_padoff[e];
        double s = 0.0;
        for (int e = 0; e < N_EXP; e++) s += (double)g_counts[e] * (double)g_psum[e];
        float aux = (float)((double)N_EXP * s / ((double)N_TOK * (double)N_TOK));
        if (out_size > N_TOK * D_MODEL) out[(size_t)N_TOK * D_MODEL] = aux;
    }
    __syncthreads();
    for (int j = tid; j < NT_DN; j += blockDim.x) {
        int row = j * 256, te = -1;
#pragma unroll
        for (int e = 0; e < N_EXP; e++)
            if (row >= spad[e] && row < spad[e + 1]) te = e;
        g_tile_dn[j] = te;
    }
}

__global__ void scatter_kernel() {
    int t = blockIdx.x * blockDim.x + threadIdx.x;
    if (t >= N_TOK) return;
#pragma unroll
    for (int k = 0; k < 2; k++) {
        int e = g_tok_idx[t * 2 + k];
        int pos = atomicAdd(&g_fill[e], 1);
        int slot = g_padoff[e] + pos;
        g_slot_token[slot] = t;
        g_tok_slot[t * 2 + k] = slot;
    }
}

// ---------------- conversions --------------------------------------------------
__global__ void conv_x_kernel(const float* __restrict__ x) {
    int i = blockIdx.x * 256 + threadIdx.x;
    g_Xh[i] = __float2half(x[i]);
}

// gate+up -> interleaved [slab][4096 n][1024 k] fp16
__global__ void conv_gu_kernel(const float* __restrict__ srcGs, const float* __restrict__ srcGe,
                               const float* __restrict__ srcUs, const float* __restrict__ srcUe,
                               __half* __restrict__ o) {
    int slab = blockIdx.z;
    const float* G = (slab == 0) ? srcGs : srcGe + (size_t)(slab - 1) * D_MODEL * D_FFN;
    const float* U = (slab == 0) ? srcUs : srcUe + (size_t)(slab - 1) * D_MODEL * D_FFN;
    size_t ob = (size_t)slab * 2 * D_FFN * D_MODEL;
    __shared__ float tg[32][33], tu[32][33];
    int tx = threadIdx.x & 31, ty = threadIdx.x >> 5;
    int k0 = blockIdx.y * 32, j0 = blockIdx.x * 32;
#pragma unroll
    for (int p = 0; p < 4; p++) {
        size_t so = (size_t)(k0 + p * 8 + ty) * D_FFN + j0 + tx;
        tg[p * 8 + ty][tx] = G[so];
        tu[p * 8 + ty][tx] = U[so];
    }
    __syncthreads();
    int nG0 = ((j0 >> 6) << 7) + (j0 & 63);
#pragma unroll
    for (int p = 0; p < 4; p++) {
        int jj = p * 8 + ty, k = k0 + tx;
        o[ob + (size_t)(nG0 + jj) * D_MODEL + k]      = __float2half(tg[tx][jj]);
        o[ob + (size_t)(nG0 + 64 + jj) * D_MODEL + k] = __float2half(tu[tx][jj]);
    }
}

// down: transpose [R,C] fp32 -> [slab][C][R] fp16
__global__ void conv_w_kernel(const float* __restrict__ srcS, const float* __restrict__ srcE,
                              __half* __restrict__ o, int R, int C) {
    int slab = blockIdx.z;
    const float* src = (slab == 0) ? srcS : srcE + (size_t)(slab - 1) * R * C;
    size_t ob = (size_t)slab * R * C;
    __shared__ float t[32][33];
    int tx = threadIdx.x & 31, ty = threadIdx.x >> 5;
    int r0 = blockIdx.y * 32, c0 = blockIdx.x * 32;
#pragma unroll
    for (int p = 0; p < 4; p++)
        t[p * 8 + ty][tx] = src[(size_t)(r0 + p * 8 + ty) * C + c0 + tx];
    __syncthreads();
#pragma unroll
    for (int p = 0; p < 4; p++) {
        int n = c0 + p * 8 + ty, k = r0 + tx;
        o[ob + (size_t)n * R + k] = __float2half(t[tx][p * 8 + ty]);
    }
}

// ---------------- gate+up GEMM: 256M x 128N(=64G+64U) ---------------------------
// 512 threads = 16 warps (8M x 2N), warp tile 32x64. 3-stage cp.async ring.
__global__ void __launch_bounds__(512, 1) mma_gateup_kernel() {
    const int by = blockIdx.y;
    const bool sh = (by < NT_SH);
    int te = 0, r0;
    if (sh) r0 = by * 256;
    else {
        int be = by - NT_SH;
        te = g_tile_dn[be];
        if (te < 0) return;
        r0 = be * 256;
    }
    const int slab = sh ? 0 : 1 + te;
    const int n0b = blockIdx.x * 128;        // interleaved B row base
    const int h0 = blockIdx.x * 64;          // H column base
    const int tid = threadIdx.x, lane = tid & 31, wid = tid >> 5;
    const int wm = wid & 7, wn = wid >> 3;

    extern __shared__ __align__(16) char smem[];
    __shared__ int stok[256];
    const uint32_t sbase = s2u(smem);

    if (tid < 256) {
        if (sh) stok[tid] = r0 + tid;
        else { int t = g_slot_token[r0 + tid]; stok[tid] = t < 0 ? 0 : t; }
    }
    __syncthreads();

    const __half* __restrict__ B = g_Bgu + (size_t)slab * 2 * D_FFN * D_MODEL;

    auto load_stage = [&](int s) {
        const int k0 = s << 5;
        const uint32_t st = sbase + (s % 3) * STG_B;
        {   // A: 256 rows x 4 x 16B -> 1024 cpa16 / 512 thr = 2 each
            int row = tid >> 1, ch = tid & 1;
#pragma unroll
            for (int half = 0; half < 2; half++) {
                uint32_t off = row * 80 + (ch * 2 + half) * 16;
                cpa16(st + off,
                      g_Xh + (size_t)stok[row] * D_MODEL + k0 + (ch * 2 + half) * 8);
            }
        }
        {   // B: 128 rows x 4 x 16B -> 512 cpa16 / 512 thr = 1 each
            int row = tid >> 2, ch = tid & 3;
            cpa16(st + A_TILE + row * 80 + ch * 16,
                  B + (size_t)(n0b + row) * D_MODEL + k0 + ch * 8);
        }
        cp_commit();
    };

    float acc[2][8][4];
#pragma unroll
    for (int i = 0; i < 2; i++)
#pragma unroll
        for (int j = 0; j < 8; j++)
#pragma unroll
            for (int q = 0; q < 4; q++) acc[i][j][q] = 0.f;

    load_stage(0); load_stage(1);
    for (int s = 0; s < GU_NSTG; s++) {
        cp_wait<1>();
        __syncthreads();
        if (s + 2 < GU_NSTG) load_stage(s + 2); else cp_commit();
        const uint32_t st = sbase + (s % 3) * STG_B;
        const int lr = lane & 15, lc = (lane >> 4) * 16;
#pragma unroll
        for (int kh = 0; kh < 2; kh++) {
            const int kb = kh * 32 + lc;
            uint32_t a[2][4];
#pragma unroll
            for (int mi = 0; mi < 2; mi++)
                ldm4(a[mi], st + (wm * 32 + mi * 16 + lr) * 80 + kb);
#pragma unroll
            for (int nj = 0; nj < 4; nj++) {
                uint32_t bf[4];
                ldm4(bf, st + A_TILE + (wn * 64 + nj * 16 + lr) * 80 + kb);
#pragma unroll
                for (int mi = 0; mi < 2; mi++) {
                    mma_f16(acc[mi][nj * 2],     a[mi], bf[0], bf[2]);
                    mma_f16(acc[mi][nj * 2 + 1], a[mi], bf[1], bf[3]);
                }
            }
        }
    }

    // SwiGLU epilogue: G warps (wn=0) hand accumulators to U warps (wn=1) via smem
    __syncthreads();
    float* gbuf = (float*)smem;   // 256 rows x 66 floats = 67584 B (< MM_SMEM)
    if (wn == 0) {
#pragma unroll
        for (int mi = 0; mi < 2; mi++)
#pragma unroll
            for (int ni = 0; ni < 8; ni++)
#pragma unroll
                for (int hh = 0; hh < 2; hh++) {
                    int row = wm * 32 + mi * 16 + (lane >> 2) + hh * 8;
                    int col = ni * 8 + 2 * (lane & 3);
                    float2 v; v.x = acc[mi][ni][hh * 2]; v.y = acc[mi][ni][hh * 2 + 1];
                    *(float2*)(gbuf + row * 66 + col) = v;
                }
    }
    __syncthreads();
    if (wn == 1) {
        __half* __restrict__ H = sh ? g_Hs : g_He;
#pragma unroll
        for (int mi = 0; mi < 2; mi++)
#pragma unroll
            for (int ni = 0; ni < 8; ni++)
#pragma unroll
                for (int hh = 0; hh < 2; hh++) {
                    int row = wm * 32 + mi * 16 + (lane >> 2) + hh * 8;
                    int col = ni * 8 + 2 * (lane & 3);
                    float2 g2 = *(const float2*)(gbuf + row * 66 + col);
                    float u0 = acc[mi][ni][hh * 2], u1 = acc[mi][ni][hh * 2 + 1];
                    float h0v = g2.x / (1.f + expf(-g2.x)) * u0;
                    float h1v = g2.y / (1.f + expf(-g2.y)) * u1;
                    __half2 hv;
                    hv.x = __float2half(h0v);
                    hv.y = __float2half(h1v);
                    *(__half2*)(H + (size_t)(r0 + row) * D_FFN + h0 + col) = hv;
                }
    }
}

// ---------------- down GEMM: 256M x 128N -----------------------------------------
__global__ void __launch_bounds__(512, 1) mma_down_kernel() {
    const int by = blockIdx.y;
    const bool sh = (by < NT_SH);
    int te = 0, r0;
    if (sh) r0 = by * 256;
    else {
        int be = by - NT_SH;
        te = g_tile_dn[be];
        if (te < 0) return;
        r0 = be * 256;
    }
    const int slab = sh ? 0 : 1 + te;
    const int n0 = blockIdx.x * 128;
    const int tid = threadIdx.x, lane = tid & 31, wid = tid >> 5;
    const int wm = wid & 7, wn = wid >> 3;

    extern __shared__ __align__(16) char smem[];
    const uint32_t sbase = s2u(smem);

    const __half* __restrict__ Ah = sh ? g_Hs : g_He;
    const __half* __restrict__ B = g_Bd + (size_t)slab * D_MODEL * D_FFN;

    auto load_stage = [&](int s) {
        const int k0 = s << 5;
        const uint32_t st = sbase + (s % 3) * STG_B;
        {
            int row = tid >> 1, ch = tid & 1;
#pragma unroll
            for (int half = 0; half < 2; half++) {
                uint32_t off = row * 80 + (ch * 2 + half) * 16;
                cpa16(st + off,
                      Ah + (size_t)(r0 + row) * D_FFN + k0 + (ch * 2 + half) * 8);
            }
        }
        {
            int row = tid >> 2, ch = tid & 3;
            cpa16(st + A_TILE + row * 80 + ch * 16,
                  B + (size_t)(n0 + row) * D_FFN + k0 + ch * 8);
        }
        cp_commit();
    };

    float acc[2][8][4];
#pragma unroll
    for (int i = 0; i < 2; i++)
#pragma unroll
        for (int j = 0; j < 8; j++)
#pragma unroll
            for (int q = 0; q < 4; q++) acc[i][j][q] = 0.f;

    load_stage(0); load_stage(1);
    for (int s = 0; s < DN_NSTG; s++) {
        cp_wait<1>();
        __syncthreads();
        if (s + 2 < DN_NSTG) load_stage(s + 2); else cp_commit();
        const uint32_t st = sbase + (s % 3) * STG_B;
        const int lr = lane & 15, lc = (lane >> 4) * 16;
#pragma unroll
        for (int kh = 0; kh < 2; kh++) {
            const int kb = kh * 32 + lc;
            uint32_t a[2][4];
#pragma unroll
            for (int mi = 0; mi < 2; mi++)
                ldm4(a[mi], st + (wm * 32 + mi * 16 + lr) * 80 + kb);
#pragma unroll
            for (int nj = 0; nj < 4; nj++) {
                uint32_t bf[4];
                ldm4(bf, st + A_TILE + (wn * 64 + nj * 16 + lr) * 80 + kb);
#pragma unroll
                for (int mi = 0; mi < 2; mi++) {
                    mma_f16(acc[mi][nj * 2],     a[mi], bf[0], bf[2]);
                    mma_f16(acc[mi][nj * 2 + 1], a[mi], bf[1], bf[3]);
                }
            }
        }
    }

    float* __restrict__ O = sh ? g_Os : g_Oe;
#pragma unroll
    for (int mi = 0; mi < 2; mi++)
#pragma unroll
        for (int ni = 0; ni < 8; ni++)
#pragma unroll
            for (int hh = 0; hh < 2; hh++) {
                int row = wm * 32 + mi * 16 + (lane >> 2) + hh * 8;
                int col = n0 + wn * 64 + ni * 8 + 2 * (lane & 3);
                float2 v; v.x = acc[mi][ni][hh * 2]; v.y = acc[mi][ni][hh * 2 + 1];
                *(float2*)(O + (size_t)(r0 + row) * D_MODEL + col) = v;
            }
}

// ---------------- combine: out = Os + w0*Oe[s0] + w1*Oe[s1] -----------------------
__global__ void combine_kernel(float* __restrict__ out) {
    int t = blockIdx.x;
    int tid = threadIdx.x;
    int s0 = g_tok_slot[t * 2 + 0], s1 = g_tok_slot[t * 2 + 1];
    float w0 = g_tok_w[t * 2 + 0],  w1 = g_tok_w[t * 2 + 1];
    const float4* a = (const float4*)(g_Os + (size_t)t * D_MODEL) + tid;
    const float4* b = (const float4*)(g_Oe + (size_t)s0 * D_MODEL) + tid;
    const float4* c = (const float4*)(g_Oe + (size_t)s1 * D_MODEL) + tid;
    float4 va = *a, vb = *b, vc = *c;
    float4 r;
    r.x = va.x + w0 * vb.x + w1 * vc.x;
    r.y = va.y + w0 * vb.y + w1 * vc.y;
    r.z = va.z + w0 * vb.z + w1 * vc.z;
    r.w = va.w + w0 * vb.w + w1 * vc.w;
    *((float4*)(out + (size_t)t * D_MODEL) + tid) = r;
}

// ---------------- launch ------------------------------------------------------------
extern "C" void kernel_launch(void* const* d_in, const int* in_sizes, int n_in,
                              void* d_out, int out_size) {
    const float* x         = (const float*)d_in[0];
    const float* shared_wg = (const float*)d_in[1];
    const float* shared_wu = (const float*)d_in[2];
    const float* shared_wd = (const float*)d_in[3];
    const float* exp_wg    = (const float*)d_in[4];
    const float* exp_wu    = (const float*)d_in[5];
    const float* exp_wd    = (const float*)d_in[6];
    const float* router_w  = (const float*)d_in[7];
    float* out = (float*)d_out;

    __half *bgu, *bd;
    cudaGetSymbolAddress((void**)&bgu, g_Bgu);
    cudaGetSymbolAddress((void**)&bd, g_Bd);

    cudaFuncSetAttribute(mma_gateup_kernel,
                         cudaFuncAttributeMaxDynamicSharedMemorySize, MM_SMEM);
    cudaFuncSetAttribute(mma_down_kernel,
                         cudaFuncAttributeMaxDynamicSharedMemorySize, MM_SMEM);

    init_kernel<<<(MAXSLOT + 255) / 256, 256>>>();
    router_kernel<<<N_TOK / 4, 128>>>(x, router_w);
    offsets_kernel<<<1, 128>>>(out, out_size);
    scatter_kernel<<<N_TOK / 256, 256>>>();

    conv_x_kernel<<<(N_TOK * D_MODEL) / 256, 256>>>(x);
    conv_gu_kernel<<<dim3(D_FFN / 32, D_MODEL / 32, 9), 256>>>(
        shared_wg, exp_wg, shared_wu, exp_wu, bgu);
    conv_w_kernel<<<dim3(D_MODEL / 32, D_FFN / 32, 9), 256>>>(
        shared_wd, exp_wd, bd, D_FFN, D_MODEL);

    mma_gateup_kernel<<<dim3(D_FFN / 64, NT_SH + NT_DN), 512, MM_SMEM>>>();
    mma_down_kernel<<<dim3(D_MODEL / 128, NT_SH + NT_DN), 512, MM_SMEM>>>();
    combine_kernel<<<N_TOK, 256>>>(out);
}

// round 13
// speedup vs baseline: 1.0144x; 1.0144x over previous
#include <cuda_runtime.h>
#include <cuda_fp16.h>
#include <math.h>
#include <stdint.h>

#define D_MODEL 1024
#define D_FFN   2048
#define N_TOK   4096
#define N_EXP   8
#define MAXSLOT 9216
#define NT_SH   (N_TOK / 128)     /* 32 shared row tiles */
#define NT_DN   (MAXSLOT / 128)   /* 72 expert row tiles */

#define ROWB    144               /* 128B of K data + 16B pad */
#define TILE_B  (128 * ROWB)      /* 18432 */
#define STG_B   (2 * TILE_B)      /* A, B = 36864 */
#define MM_SMEM (2 * STG_B)       /* 73728, 2-stage ring */
#define GU_NSTG 16                /* K=1024 / 64 */
#define DN_NSTG 32                /* K=2048 / 64 */

// ---------------- scratch ----------------------------------------------------
__device__ __half g_Xh[(size_t)N_TOK * D_MODEL];
// gate+up interleaved: [slab][4096 n][1024 k]; n-chunk c (128 wide) = G cols
// [64c,64c+64) at +0..63, U cols [64c,64c+64) at +64..127
__device__ __half g_Bgu[(size_t)9 * 2 * D_FFN * D_MODEL];
__device__ __half g_Bd[(size_t)9 * D_MODEL * D_FFN];
__device__ __half g_Hs[(size_t)N_TOK * D_FFN];
__device__ __half g_He[(size_t)MAXSLOT * D_FFN];
__device__ float g_Os[(size_t)N_TOK * D_MODEL];
__device__ float g_Oe[(size_t)MAXSLOT * D_MODEL];
__device__ int   g_slot_token[MAXSLOT];
__device__ int   g_counts[N_EXP];
__device__ float g_psum[N_EXP];
__device__ int   g_fill[N_EXP];
__device__ int   g_padoff[N_EXP + 1];
__device__ int   g_tile_dn[NT_DN];
__device__ int   g_tok_idx[N_TOK * 2];
__device__ int   g_tok_slot[N_TOK * 2];
__device__ float g_tok_w[N_TOK * 2];

// ---------------- PTX helpers -------------------------------------------------
__device__ __forceinline__ uint32_t s2u(const void* p) {
    return (uint32_t)__cvta_generic_to_shared(p);
}
__device__ __forceinline__ void cpa16(uint32_t dst, const void* src) {
    asm volatile("cp.async.cg.shared.global [%0], [%1], 16;" :: "r"(dst), "l"(src));
}
__device__ __forceinline__ void cp_commit() {
    asm volatile("cp.async.commit_group;");
}
template <int N>
__device__ __forceinline__ void cp_wait() {
    asm volatile("cp.async.wait_group %0;" :: "n"(N));
}
__device__ __forceinline__ void ldm4(uint32_t* r, uint32_t addr) {
    asm volatile("ldmatrix.sync.aligned.m8n8.x4.shared.b16 {%0,%1,%2,%3}, [%4];"
                 : "=r"(r[0]), "=r"(r[1]), "=r"(r[2]), "=r"(r[3]) : "r"(addr));
}
__device__ __forceinline__ void mma_f16(float* c, const uint32_t* a,
                                        uint32_t b0, uint32_t b1) {
    asm volatile("mma.sync.aligned.m16n8k16.row.col.f32.f16.f16.f32 "
                 "{%0,%1,%2,%3}, {%4,%5,%6,%7}, {%8,%9}, {%0,%1,%2,%3};"
                 : "+f"(c[0]), "+f"(c[1]), "+f"(c[2]), "+f"(c[3])
                 : "r"(a[0]), "r"(a[1]), "r"(a[2]), "r"(a[3]), "r"(b0), "r"(b1));
}

// ---------------- routing kernels ---------------------------------------------
__global__ void init_kernel() {
    int i = blockIdx.x * blockDim.x + threadIdx.x;
    if (i < MAXSLOT) g_slot_token[i] = -1;
    if (i < N_EXP) { g_counts[i] = 0; g_psum[i] = 0.f; g_fill[i] = 0; }
}

__global__ void router_kernel(const float* __restrict__ x,
                              const float* __restrict__ rw) {
    int t = blockIdx.x * 4 + (threadIdx.x >> 5);
    int lane = threadIdx.x & 31;
    if (t >= N_TOK) return;
    const float* xr = x + (size_t)t * D_MODEL;
    float acc[N_EXP];
#pragma unroll
    for (int e = 0; e < N_EXP; e++) acc[e] = 0.f;
    for (int k = lane; k < D_MODEL; k += 32) {
        float xv = xr[k];
#pragma unroll
        for (int e = 0; e < N_EXP; e++) acc[e] += xv * rw[k * N_EXP + e];
    }
#pragma unroll
    for (int e = 0; e < N_EXP; e++)
#pragma unroll
        for (int o = 16; o; o >>= 1) acc[e] += __shfl_xor_sync(0xffffffffu, acc[e], o);
    if (lane == 0) {
        int i0 = 0; float v0 = acc[0];
#pragma unroll
        for (int e = 1; e < N_EXP; e++) if (acc[e] > v0) { v0 = acc[e]; i0 = e; }
        int i1 = -1; float v1 = -1e30f;
#pragma unroll
        for (int e = 0; e < N_EXP; e++) {
            if (e == i0) continue;
            if (acc[e] > v1) { v1 = acc[e]; i1 = e; }
        }
        float m2 = fmaxf(v0, v1);
        float e0 = expf(v0 - m2), e1 = expf(v1 - m2);
        float inv = 1.f / (e0 + e1);
        g_tok_idx[t * 2 + 0] = i0;  g_tok_w[t * 2 + 0] = e0 * inv;
        g_tok_idx[t * 2 + 1] = i1;  g_tok_w[t * 2 + 1] = e1 * inv;
        atomicAdd(&g_counts[i0], 1);
        atomicAdd(&g_counts[i1], 1);
        float mm = acc[0];
#pragma unroll
        for (int e = 1; e < N_EXP; e++) mm = fmaxf(mm, acc[e]);
        float s = 0.f, ex[N_EXP];
#pragma unroll
        for (int e = 0; e < N_EXP; e++) { ex[e] = expf(acc[e] - mm); s += ex[e]; }
        float invs = 1.f / s;
#pragma unroll
        for (int e = 0; e < N_EXP; e++) atomicAdd(&g_psum[e], ex[e] * invs);
    }
}

__global__ void offsets_kernel(float* __restrict__ out, int out_size) {
    __shared__ int spad[N_EXP + 1];
    int tid = threadIdx.x;
    if (tid == 0) {
        int off = 0;
        for (int e = 0; e < N_EXP; e++) {
            g_padoff[e] = off;
            off += ((g_counts[e] + 127) / 128) * 128;
        }
        g_padoff[N_EXP] = off;
        for (int e = 0; e <= N_EXP; e++) spad[e] = g_padoff[e];
        double s = 0.0;
        for (int e = 0; e < N_EXP; e++) s += (double)g_counts[e] * (double)g_psum[e];
        float aux = (float)((double)N_EXP * s / ((double)N_TOK * (double)N_TOK));
        if (out_size > N_TOK * D_MODEL) out[(size_t)N_TOK * D_MODEL] = aux;
    }
    __syncthreads();
    for (int j = tid; j < NT_DN; j += blockDim.x) {
        int row = j * 128, te = -1;
#pragma unroll
        for (int e = 0; e < N_EXP; e++)
            if (row >= spad[e] && row < spad[e + 1]) te = e;
        g_tile_dn[j] = te;
    }
}

__global__ void scatter_kernel() {
    int t = blockIdx.x * blockDim.x + threadIdx.x;
    if (t >= N_TOK) return;
#pragma unroll
    for (int k = 0; k < 2; k++) {
        int e = g_tok_idx[t * 2 + k];
        int pos = atomicAdd(&g_fill[e], 1);
        int slot = g_padoff[e] + pos;
        g_slot_token[slot] = t;
        g_tok_slot[t * 2 + k] = slot;
    }
}

// ---------------- conversions --------------------------------------------------
__global__ void conv_x_kernel(const float* __restrict__ x) {
    int i = blockIdx.x * 256 + threadIdx.x;
    g_Xh[i] = __float2half(x[i]);
}

// gate+up -> interleaved [slab][4096 n][1024 k] fp16
__global__ void conv_gu_kernel(const float* __restrict__ srcGs, const float* __restrict__ srcGe,
                               const float* __restrict__ srcUs, const float* __restrict__ srcUe,
                               __half* __restrict__ o) {
    int slab = blockIdx.z;
    const float* G = (slab == 0) ? srcGs : srcGe + (size_t)(slab - 1) * D_MODEL * D_FFN;
    const float* U = (slab == 0) ? srcUs : srcUe + (size_t)(slab - 1) * D_MODEL * D_FFN;
    size_t ob = (size_t)slab * 2 * D_FFN * D_MODEL;
    __shared__ float tg[32][33], tu[32][33];
    int tx = threadIdx.x & 31, ty = threadIdx.x >> 5;
    int k0 = blockIdx.y * 32, j0 = blockIdx.x * 32;
#pragma unroll
    for (int p = 0; p < 4; p++) {
        size_t so = (size_t)(k0 + p * 8 + ty) * D_FFN + j0 + tx;
        tg[p * 8 + ty][tx] = G[so];
        tu[p * 8 + ty][tx] = U[so];
    }
    __syncthreads();
    int nG0 = ((j0 >> 6) << 7) + (j0 & 63);
#pragma unroll
    for (int p = 0; p < 4; p++) {
        int jj = p * 8 + ty, k = k0 + tx;
        o[ob + (size_t)(nG0 + jj) * D_MODEL + k]      = __float2half(tg[tx][jj]);
        o[ob + (size_t)(nG0 + 64 + jj) * D_MODEL + k] = __float2half(tu[tx][jj]);
    }
}

// down: transpose [R,C] fp32 -> [slab][C][R] fp16
__global__ void conv_w_kernel(const float* __restrict__ srcS, const float* __restrict__ srcE,
                              __half* __restrict__ o, int R, int C) {
    int slab = blockIdx.z;
    const float* src = (slab == 0) ? srcS : srcE + (size_t)(slab - 1) * R * C;
    size_t ob = (size_t)slab * R * C;
    __shared__ float t[32][33];
    int tx = threadIdx.x & 31, ty = threadIdx.x >> 5;
    int r0 = blockIdx.y * 32, c0 = blockIdx.x * 32;
#pragma unroll
    for (int p = 0; p < 4; p++)
        t[p * 8 + ty][tx] = src[(size_t)(r0 + p * 8 + ty) * C + c0 + tx];
    __syncthreads();
#pragma unroll
    for (int p = 0; p < 4; p++) {
        int n = c0 + p * 8 + ty, k = r0 + tx;
        o[ob + (size_t)n * R + k] = __float2half(t[tx][p * 8 + ty]);
    }
}

// ---------------- gate+up GEMM: 128M x 128N(=64G+64U), K-stage 64 ---------------
__global__ void __launch_bounds__(256, 2) mma_gateup_kernel() {
    const int by = blockIdx.y;
    const bool sh = (by < NT_SH);
    int te = 0, r0;
    if (sh) r0 = by * 128;
    else {
        int be = by - NT_SH;
        te = g_tile_dn[be];
        if (te < 0) return;
        r0 = be * 128;
    }
    const int slab = sh ? 0 : 1 + te;
    const int n0b = blockIdx.x * 128;        // interleaved B row base
    const int h0 = blockIdx.x * 64;          // H column base
    const int tid = threadIdx.x, lane = tid & 31, wid = tid >> 5;
    const int wm = wid & 3, wn = wid >> 2;

    extern __shared__ __align__(16) char smem[];
    __shared__ int stok[128];
    const uint32_t sbase = s2u(smem);

    if (tid < 128) {
        if (sh) stok[tid] = r0 + tid;
        else { int t = g_slot_token[r0 + tid]; stok[tid] = t < 0 ? 0 : t; }
    }
    __syncthreads();

    const __half* __restrict__ B = g_Bgu + (size_t)slab * 2 * D_FFN * D_MODEL;

    auto load_stage = [&](int s) {
        const int k0 = s << 6;
        const uint32_t st = sbase + (s & 1) * STG_B;
        int row = tid >> 1, g = tid & 1;
        size_t arow = (size_t)stok[row] * D_MODEL + k0;
        size_t brow = (size_t)(n0b + row) * D_MODEL + k0;
#pragma unroll
        for (int q = 0; q < 4; q++) {
            int ch = g * 4 + q;
            uint32_t off = row * ROWB + ch * 16;
            cpa16(st + off,          g_Xh + arow + ch * 8);
            cpa16(st + TILE_B + off, B + brow + ch * 8);
        }
        cp_commit();
    };

    float acc[2][8][4];
#pragma unroll
    for (int i = 0; i < 2; i++)
#pragma unroll
        for (int j = 0; j < 8; j++)
#pragma unroll
            for (int q = 0; q < 4; q++) acc[i][j][q] = 0.f;

    load_stage(0);
    for (int s = 0; s < GU_NSTG; s++) {
        cp_wait<0>();
        __syncthreads();
        if (s + 1 < GU_NSTG) load_stage(s + 1);
        const uint32_t st = sbase + (s & 1) * STG_B;
        const int lr = lane & 15, lc = (lane >> 4) * 16;
#pragma unroll
        for (int kh = 0; kh < 4; kh++) {
            const int kb = kh * 32 + lc;
            uint32_t a[2][4];
#pragma unroll
            for (int mi = 0; mi < 2; mi++)
                ldm4(a[mi], st + (wm * 32 + mi * 16 + lr) * ROWB + kb);
#pragma unroll
            for (int nj = 0; nj < 4; nj++) {
                uint32_t bf[4];
                ldm4(bf, st + TILE_B + (wn * 64 + nj * 16 + lr) * ROWB + kb);
#pragma unroll
                for (int mi = 0; mi < 2; mi++) {
                    mma_f16(acc[mi][nj * 2],     a[mi], bf[0], bf[2]);
                    mma_f16(acc[mi][nj * 2 + 1], a[mi], bf[1], bf[3]);
                }
            }
        }
    }

    // SwiGLU epilogue: G warps (wn=0) hand accumulators to U warps (wn=1) via smem
    __syncthreads();
    float* gbuf = (float*)smem;
    if (wn == 0) {
#pragma unroll
        for (int mi = 0; mi < 2; mi++)
#pragma unroll
            for (int ni = 0; ni < 8; ni++)
#pragma unroll
                for (int hh = 0; hh < 2; hh++) {
                    int row = wm * 32 + mi * 16 + (lane >> 2) + hh * 8;
                    int col = ni * 8 + 2 * (lane & 3);
                    float2 v; v.x = acc[mi][ni][hh * 2]; v.y = acc[mi][ni][hh * 2 + 1];
                    *(float2*)(gbuf + row * 66 + col) = v;
                }
    }
    __syncthreads();
    if (wn == 1) {
        __half* __restrict__ H = sh ? g_Hs : g_He;
#pragma unroll
        for (int mi = 0; mi < 2; mi++)
#pragma unroll
            for (int ni = 0; ni < 8; ni++)
#pragma unroll
                for (int hh = 0; hh < 2; hh++) {
                    int row = wm * 32 + mi * 16 + (lane >> 2) + hh * 8;
                    int col = ni * 8 + 2 * (lane & 3);
                    float2 g2 = *(const float2*)(gbuf + row * 66 + col);
                    float u0 = acc[mi][ni][hh * 2], u1 = acc[mi][ni][hh * 2 + 1];
                    float h0v = g2.x / (1.f + expf(-g2.x)) * u0;
                    float h1v = g2.y / (1.f + expf(-g2.y)) * u1;
                    __half2 hv;
                    hv.x = __float2half(h0v);
                    hv.y = __float2half(h1v);
                    *(__half2*)(H + (size_t)(r0 + row) * D_FFN + h0 + col) = hv;
                }
    }
}

// ---------------- down GEMM: 128M x 128N, K-stage 64 -----------------------------
__global__ void __launch_bounds__(256, 2) mma_down_kernel() {
    const int by = blockIdx.y;
    const bool sh = (by < NT_SH);
    int te = 0, r0;
    if (sh) r0 = by * 128;
    else {
        int be = by - NT_SH;
        te = g_tile_dn[be];
        if (te < 0) return;
        r0 = be * 128;
    }
    const int slab = sh ? 0 : 1 + te;
    const int n0 = blockIdx.x * 128;
    const int tid = threadIdx.x, lane = tid & 31, wid = tid >> 5;
    const int wm = wid & 3, wn = wid >> 2;

    extern __shared__ __align__(16) char smem[];
    const uint32_t sbase = s2u(smem);

    const __half* __restrict__ Ah = sh ? g_Hs : g_He;
    const __half* __restrict__ B = g_Bd + (size_t)slab * D_MODEL * D_FFN;

    auto load_stage = [&](int s) {
        const int k0 = s << 6;
        const uint32_t st = sbase + (s & 1) * STG_B;
        int row = tid >> 1, g = tid & 1;
        size_t arow = (size_t)(r0 + row) * D_FFN + k0;
        size_t brow = (size_t)(n0 + row) * D_FFN + k0;
#pragma unroll
        for (int q = 0; q < 4; q++) {
            int ch = g * 4 + q;
            uint32_t off = row * ROWB + ch * 16;
            cpa16(st + off,          Ah + arow + ch * 8);
            cpa16(st + TILE_B + off, B + brow + ch * 8);
        }
        cp_commit();
    };

    float acc[2][8][4];
#pragma unroll
    for (int i = 0; i < 2; i++)
#pragma unroll
        for (int j = 0; j < 8; j++)
#pragma unroll
            for (int q = 0; q < 4; q++) acc[i][j][q] = 0.f;

    load_stage(0);
    for (int s = 0; s < DN_NSTG; s++) {
        cp_wait<0>();
        __syncthreads();
        if (s + 1 < DN_NSTG) load_stage(s + 1);
        const uint32_t st = sbase + (s & 1) * STG_B;
        const int lr = lane & 15, lc = (lane >> 4) * 16;
#pragma unroll
        for (int kh = 0; kh < 4; kh++) {
            const int kb = kh * 32 + lc;
            uint32_t a[2][4];
#pragma unroll
            for (int mi = 0; mi < 2; mi++)
                ldm4(a[mi], st + (wm * 32 + mi * 16 + lr) * ROWB + kb);
#pragma unroll
            for (int nj = 0; nj < 4; nj++) {
                uint32_t bf[4];
                ldm4(bf, st + TILE_B + (wn * 64 + nj * 16 + lr) * ROWB + kb);
#pragma unroll
                for (int mi = 0; mi < 2; mi++) {
                    mma_f16(acc[mi][nj * 2],     a[mi], bf[0], bf[2]);
                    mma_f16(acc[mi][nj * 2 + 1], a[mi], bf[1], bf[3]);
                }
            }
        }
    }

    float* __restrict__ O = sh ? g_Os : g_Oe;
#pragma unroll
    for (int mi = 0; mi < 2; mi++)
#pragma unroll
        for (int ni = 0; ni < 8; ni++)
#pragma unroll
            for (int hh = 0; hh < 2; hh++) {
                int row = wm * 32 + mi * 16 + (lane >> 2) + hh * 8;
                int col = n0 + wn * 64 + ni * 8 + 2 * (lane & 3);
                float2 v; v.x = acc[mi][ni][hh * 2]; v.y = acc[mi][ni][hh * 2 + 1];
                *(float2*)(O + (size_t)(r0 + row) * D_MODEL + col) = v;
            }
}

// ---------------- combine: out = Os + w0*Oe[s0] + w1*Oe[s1] -----------------------
__global__ void combine_kernel(float* __restrict__ out) {
    int t = blockIdx.x;
    int tid = threadIdx.x;
    int s0 = g_tok_slot[t * 2 + 0], s1 = g_tok_slot[t * 2 + 1];
    float w0 = g_tok_w[t * 2 + 0],  w1 = g_tok_w[t * 2 + 1];
    const float4* a = (const float4*)(g_Os + (size_t)t * D_MODEL) + tid;
    const float4* b = (const float4*)(g_Oe + (size_t)s0 * D_MODEL) + tid;
    const float4* c = (const float4*)(g_Oe + (size_t)s1 * D_MODEL) + tid;
    float4 va = *a, vb = *b, vc = *c;
    float4 r;
    r.x = va.x + w0 * vb.x + w1 * vc.x;
    r.y = va.y + w0 * vb.y + w1 * vc.y;
    r.z = va.z + w0 * vb.z + w1 * vc.z;
    r.w = va.w + w0 * vb.w + w1 * vc.w;
    *((float4*)(out + (size_t)t * D_MODEL) + tid) = r;
}

// ---------------- launch ------------------------------------------------------------
extern "C" void kernel_launch(void* const* d_in, const int* in_sizes, int n_in,
                              void* d_out, int out_size) {
    const float* x         = (const float*)d_in[0];
    const float* shared_wg = (const float*)d_in[1];
    const float* shared_wu = (const float*)d_in[2];
    const float* shared_wd = (const float*)d_in[3];
    const float* exp_wg    = (const float*)d_in[4];
    const float* exp_wu    = (const float*)d_in[5];
    const float* exp_wd    = (const float*)d_in[6];
    const float* router_w  = (const float*)d_in[7];
    float* out = (float*)d_out;

    __half *bgu, *bd;
    cudaGetSymbolAddress((void**)&bgu, g_Bgu);
    cudaGetSymbolAddress((void**)&bd, g_Bd);

    cudaFuncSetAttribute(mma_gateup_kernel,
                         cudaFuncAttributeMaxDynamicSharedMemorySize, MM_SMEM);
    cudaFuncSetAttribute(mma_down_kernel,
                         cudaFuncAttributeMaxDynamicSharedMemorySize, MM_SMEM);

    init_kernel<<<(MAXSLOT + 255) / 256, 256>>>();
    router_kernel<<<N_TOK / 4, 128>>>(x, router_w);
    offsets_kernel<<<1, 128>>>(out, out_size);
    scatter_kernel<<<N_TOK / 256, 256>>>();

    conv_x_kernel<<<(N_TOK * D_MODEL) / 256, 256>>>(x);
    conv_gu_kernel<<<dim3(D_FFN / 32, D_MODEL / 32, 9), 256>>>(
        shared_wg, exp_wg, shared_wu, exp_wu, bgu);
    conv_w_kernel<<<dim3(D_MODEL / 32, D_FFN / 32, 9), 256>>>(
        shared_wd, exp_wd, bd, D_FFN, D_MODEL);

    mma_gateup_kernel<<<dim3(D_FFN / 64, NT_SH + NT_DN), 256, MM_SMEM>>>();
    mma_down_kernel<<<dim3(D_MODEL / 128, NT_SH + NT_DN), 256, MM_SMEM>>>();
    combine_kernel<<<N_TOK, 256>>>(out);
}

// round 14
// speedup vs baseline: 1.1262x; 1.1102x over previous
#include <cuda_runtime.h>
#include <cuda_fp16.h>
#include <math.h>
#include <stdint.h>

#define D_MODEL 1024
#define D_FFN   2048
#define N_TOK   4096
#define N_EXP   8
#define MAXSLOT 9216
#define NT_SH   (N_TOK / 128)     /* 32 shared row tiles */
#define NT_DN   (MAXSLOT / 128)   /* 72 expert row tiles */

#define TILE_B  10240             /* 128 rows * 80B (padded 64B row) */
#define STG_B   (2 * TILE_B)      /* A, B = 20480 */
#define MM_SMEM (3 * STG_B)       /* 61440, 3-stage ring */
#define GU_NSTG 32                /* K=1024 / 32 */
#define DN_NSTG 64                /* K=2048 / 32 */

// ---------------- scratch ----------------------------------------------------
__device__ __half g_Xh[(size_t)N_TOK * D_MODEL];
// gate+up interleaved: [slab][4096 n][1024 k]; n-chunk c (128 wide) = G cols
// [64c,64c+64) at +0..63, U cols [64c,64c+64) at +64..127
__device__ __half g_Bgu[(size_t)9 * 2 * D_FFN * D_MODEL];
__device__ __half g_Bd[(size_t)9 * D_MODEL * D_FFN];
__device__ __half g_Hs[(size_t)N_TOK * D_FFN];
__device__ __half g_He[(size_t)MAXSLOT * D_FFN];
__device__ float g_Os[(size_t)N_TOK * D_MODEL];
__device__ float g_Oe[(size_t)MAXSLOT * D_MODEL];
__device__ int   g_slot_token[MAXSLOT];
__device__ int   g_counts[N_EXP];
__device__ float g_psum[N_EXP];
__device__ int   g_fill[N_EXP];
__device__ int   g_padoff[N_EXP + 1];
__device__ int   g_tile_dn[NT_DN];
__device__ int   g_tok_idx[N_TOK * 2];
__device__ int   g_tok_slot[N_TOK * 2];
__device__ float g_tok_w[N_TOK * 2];

// ---------------- PTX helpers -------------------------------------------------
__device__ __forceinline__ uint32_t s2u(const void* p) {
    return (uint32_t)__cvta_generic_to_shared(p);
}
__device__ __forceinline__ void cpa16(uint32_t dst, const void* src) {
    asm volatile("cp.async.cg.shared.global [%0], [%1], 16;" :: "r"(dst), "l"(src));
}
__device__ __forceinline__ void cp_commit() {
    asm volatile("cp.async.commit_group;");
}
template <int N>
__device__ __forceinline__ void cp_wait() {
    asm volatile("cp.async.wait_group %0;" :: "n"(N));
}
__device__ __forceinline__ void ldm4(uint32_t* r, uint32_t addr) {
    asm volatile("ldmatrix.sync.aligned.m8n8.x4.shared.b16 {%0,%1,%2,%3}, [%4];"
                 : "=r"(r[0]), "=r"(r[1]), "=r"(r[2]), "=r"(r[3]) : "r"(addr));
}
__device__ __forceinline__ void mma_f16(float* c, const uint32_t* a,
                                        uint32_t b0, uint32_t b1) {
    asm volatile("mma.sync.aligned.m16n8k16.row.col.f32.f16.f16.f32 "
                 "{%0,%1,%2,%3}, {%4,%5,%6,%7}, {%8,%9}, {%0,%1,%2,%3};"
                 : "+f"(c[0]), "+f"(c[1]), "+f"(c[2]), "+f"(c[3])
                 : "r"(a[0]), "r"(a[1]), "r"(a[2]), "r"(a[3]), "r"(b0), "r"(b1));
}

// ---------------- routing kernels ---------------------------------------------
__global__ void init_kernel() {
    int i = blockIdx.x * blockDim.x + threadIdx.x;
    if (i < MAXSLOT) g_slot_token[i] = -1;
    if (i < N_EXP) { g_counts[i] = 0; g_psum[i] = 0.f; g_fill[i] = 0; }
}

__global__ void router_kernel(const float* __restrict__ x,
                              const float* __restrict__ rw) {
    int t = blockIdx.x * 4 + (threadIdx.x >> 5);
    int lane = threadIdx.x & 31;
    if (t >= N_TOK) return;
    const float* xr = x + (size_t)t * D_MODEL;
    float acc[N_EXP];
#pragma unroll
    for (int e = 0; e < N_EXP; e++) acc[e] = 0.f;
    for (int k = lane; k < D_MODEL; k += 32) {
        float xv = xr[k];
#pragma unroll
        for (int e = 0; e < N_EXP; e++) acc[e] += xv * rw[k * N_EXP + e];
    }
#pragma unroll
    for (int e = 0; e < N_EXP; e++)
#pragma unroll
        for (int o = 16; o; o >>= 1) acc[e] += __shfl_xor_sync(0xffffffffu, acc[e], o);
    if (lane == 0) {
        int i0 = 0; float v0 = acc[0];
#pragma unroll
        for (int e = 1; e < N_EXP; e++) if (acc[e] > v0) { v0 = acc[e]; i0 = e; }
        int i1 = -1; float v1 = -1e30f;
#pragma unroll
        for (int e = 0; e < N_EXP; e++) {
            if (e == i0) continue;
            if (acc[e] > v1) { v1 = acc[e]; i1 = e; }
        }
        float m2 = fmaxf(v0, v1);
        float e0 = expf(v0 - m2), e1 = expf(v1 - m2);
        float inv = 1.f / (e0 + e1);
        g_tok_idx[t * 2 + 0] = i0;  g_tok_w[t * 2 + 0] = e0 * inv;
        g_tok_idx[t * 2 + 1] = i1;  g_tok_w[t * 2 + 1] = e1 * inv;
        atomicAdd(&g_counts[i0], 1);
        atomicAdd(&g_counts[i1], 1);
        float mm = acc[0];
#pragma unroll
        for (int e = 1; e < N_EXP; e++) mm = fmaxf(mm, acc[e]);
        float s = 0.f, ex[N_EXP];
#pragma unroll
        for (int e = 0; e < N_EXP; e++) { ex[e] = expf(acc[e] - mm); s += ex[e]; }
        float invs = 1.f / s;
#pragma unroll
        for (int e = 0; e < N_EXP; e++) atomicAdd(&g_psum[e], ex[e] * invs);
    }
}

__global__ void offsets_kernel(float* __restrict__ out, int out_size) {
    __shared__ int spad[N_EXP + 1];
    int tid = threadIdx.x;
    if (tid == 0) {
        int off = 0;
        for (int e = 0; e < N_EXP; e++) {
            g_padoff[e] = off;
            off += ((g_counts[e] + 127) / 128) * 128;
        }
        g_padoff[N_EXP] = off;
        for (int e = 0; e <= N_EXP; e++) spad[e] = g_padoff[e];
        double s = 0.0;
        for (int e = 0; e < N_EXP; e++) s += (double)g_counts[e] * (double)g_psum[e];
        float aux = (float)((double)N_EXP * s / ((double)N_TOK * (double)N_TOK));
        if (out_size > N_TOK * D_MODEL) out[(size_t)N_TOK * D_MODEL] = aux;
    }
    __syncthreads();
    for (int j = tid; j < NT_DN; j += blockDim.x) {
        int row = j * 128, te = -1;
#pragma unroll
        for (int e = 0; e < N_EXP; e++)
            if (row >= spad[e] && row < spad[e + 1]) te = e;
        g_tile_dn[j] = te;
    }
}

__global__ void scatter_kernel() {
    int t = blockIdx.x * blockDim.x + threadIdx.x;
    if (t >= N_TOK) return;
#pragma unroll
    for (int k = 0; k < 2; k++) {
        int e = g_tok_idx[t * 2 + k];
        int pos = atomicAdd(&g_fill[e], 1);
        int slot = g_padoff[e] + pos;
        g_slot_token[slot] = t;
        g_tok_slot[t * 2 + k] = slot;
    }
}

// ---------------- conversions --------------------------------------------------
__global__ void conv_x_kernel(const float* __restrict__ x) {
    int i = blockIdx.x * 256 + threadIdx.x;
    g_Xh[i] = __float2half(x[i]);
}

// gate+up -> interleaved [slab][4096 n][1024 k] fp16
__global__ void conv_gu_kernel(const float* __restrict__ srcGs, const float* __restrict__ srcGe,
                               const float* __restrict__ srcUs, const float* __restrict__ srcUe,
                               __half* __restrict__ o) {
    int slab = blockIdx.z;
    const float* G = (slab == 0) ? srcGs : srcGe + (size_t)(slab - 1) * D_MODEL * D_FFN;
    const float* U = (slab == 0) ? srcUs : srcUe + (size_t)(slab - 1) * D_MODEL * D_FFN;
    size_t ob = (size_t)slab * 2 * D_FFN * D_MODEL;
    __shared__ float tg[32][33], tu[32][33];
    int tx = threadIdx.x & 31, ty = threadIdx.x >> 5;
    int k0 = blockIdx.y * 32, j0 = blockIdx.x * 32;
#pragma unroll
    for (int p = 0; p < 4; p++) {
        size_t so = (size_t)(k0 + p * 8 + ty) * D_FFN + j0 + tx;
        tg[p * 8 + ty][tx] = G[so];
        tu[p * 8 + ty][tx] = U[so];
    }
    __syncthreads();
    int nG0 = ((j0 >> 6) << 7) + (j0 & 63);
#pragma unroll
    for (int p = 0; p < 4; p++) {
        int jj = p * 8 + ty, k = k0 + tx;
        o[ob + (size_t)(nG0 + jj) * D_MODEL + k]      = __float2half(tg[tx][jj]);
        o[ob + (size_t)(nG0 + 64 + jj) * D_MODEL + k] = __float2half(tu[tx][jj]);
    }
}

// down: transpose [R,C] fp32 -> [slab][C][R] fp16
__global__ void conv_w_kernel(const float* __restrict__ srcS, const float* __restrict__ srcE,
                              __half* __restrict__ o, int R, int C) {
    int slab = blockIdx.z;
    const float* src = (slab == 0) ? srcS : srcE + (size_t)(slab - 1) * R * C;
    size_t ob = (size_t)slab * R * C;
    __shared__ float t[32][33];
    int tx = threadIdx.x & 31, ty = threadIdx.x >> 5;
    int r0 = blockIdx.y * 32, c0 = blockIdx.x * 32;
#pragma unroll
    for (int p = 0; p < 4; p++)
        t[p * 8 + ty][tx] = src[(size_t)(r0 + p * 8 + ty) * C + c0 + tx];
    __syncthreads();
#pragma unroll
    for (int p = 0; p < 4; p++) {
        int n = c0 + p * 8 + ty, k = r0 + tx;
        o[ob + (size_t)n * R + k] = __float2half(t[tx][p * 8 + ty]);
    }
}

// ---------------- gate+up GEMM: 128M x 128N(=64G+64U), 3-stage ring -------------
__global__ void __launch_bounds__(256, 2) mma_gateup_kernel() {
    const int by = blockIdx.y;
    const bool sh = (by < NT_SH);
    int te = 0, r0;
    if (sh) r0 = by * 128;
    else {
        int be = by - NT_SH;
        te = g_tile_dn[be];
        if (te < 0) return;
        r0 = be * 128;
    }
    const int slab = sh ? 0 : 1 + te;
    const int n0b = blockIdx.x * 128;        // interleaved B row base
    const int h0 = blockIdx.x * 64;          // H column base
    const int tid = threadIdx.x, lane = tid & 31, wid = tid >> 5;
    const int wm = wid & 3, wn = wid >> 2;

    extern __shared__ __align__(16) char smem[];
    __shared__ int stok[128];
    const uint32_t sbase = s2u(smem);

    if (tid < 128) {
        if (sh) stok[tid] = r0 + tid;
        else { int t = g_slot_token[r0 + tid]; stok[tid] = t < 0 ? 0 : t; }
    }
    __syncthreads();

    const __half* __restrict__ B = g_Bgu + (size_t)slab * 2 * D_FFN * D_MODEL;

    auto load_stage = [&](int s) {
        const int k0 = s << 5;
        const uint32_t st = sbase + (s % 3) * STG_B;
        {
            int row = tid >> 1, ch = tid & 1;
#pragma unroll
            for (int half = 0; half < 2; half++) {
                uint32_t off = row * 80 + (ch * 2 + half) * 16;
                cpa16(st + off,
                      g_Xh + (size_t)stok[row] * D_MODEL + k0 + (ch * 2 + half) * 8);
                cpa16(st + TILE_B + off,
                      B + (size_t)(n0b + row) * D_MODEL + k0 + (ch * 2 + half) * 8);
            }
        }
        cp_commit();
    };

    float acc[2][8][4];
#pragma unroll
    for (int i = 0; i < 2; i++)
#pragma unroll
        for (int j = 0; j < 8; j++)
#pragma unroll
            for (int q = 0; q < 4; q++) acc[i][j][q] = 0.f;

    load_stage(0); load_stage(1);
    for (int s = 0; s < GU_NSTG; s++) {
        cp_wait<1>();
        __syncthreads();
        if (s + 2 < GU_NSTG) load_stage(s + 2); else cp_commit();
        const uint32_t st = sbase + (s % 3) * STG_B;
        const int lr = lane & 15, lc = (lane >> 4) * 16;
#pragma unroll
        for (int kh = 0; kh < 2; kh++) {
            const int kb = kh * 32 + lc;
            uint32_t a[2][4];
#pragma unroll
            for (int mi = 0; mi < 2; mi++)
                ldm4(a[mi], st + (wm * 32 + mi * 16 + lr) * 80 + kb);
#pragma unroll
            for (int nj = 0; nj < 4; nj++) {
                uint32_t bf[4];
                ldm4(bf, st + TILE_B + (wn * 64 + nj * 16 + lr) * 80 + kb);
#pragma unroll
                for (int mi = 0; mi < 2; mi++) {
                    mma_f16(acc[mi][nj * 2],     a[mi], bf[0], bf[2]);
                    mma_f16(acc[mi][nj * 2 + 1], a[mi], bf[1], bf[3]);
                }
            }
        }
    }

    // SwiGLU epilogue: G warps (wn=0) hand accumulators to U warps (wn=1) via smem
    __syncthreads();
    float* gbuf = (float*)smem;
    if (wn == 0) {
#pragma unroll
        for (int mi = 0; mi < 2; mi++)
#pragma unroll
            for (int ni = 0; ni < 8; ni++)
#pragma unroll
                for (int hh = 0; hh < 2; hh++) {
                    int row = wm * 32 + mi * 16 + (lane >> 2) + hh * 8;
                    int col = ni * 8 + 2 * (lane & 3);
                    float2 v; v.x = acc[mi][ni][hh * 2]; v.y = acc[mi][ni][hh * 2 + 1];
                    *(float2*)(gbuf + row * 66 + col) = v;
                }
    }
    __syncthreads();
    if (wn == 1) {
        __half* __restrict__ H = sh ? g_Hs : g_He;
#pragma unroll
        for (int mi = 0; mi < 2; mi++)
#pragma unroll
            for (int ni = 0; ni < 8; ni++)
#pragma unroll
                for (int hh = 0; hh < 2; hh++) {
                    int row = wm * 32 + mi * 16 + (lane >> 2) + hh * 8;
                    int col = ni * 8 + 2 * (lane & 3);
                    float2 g2 = *(const float2*)(gbuf + row * 66 + col);
                    float u0 = acc[mi][ni][hh * 2], u1 = acc[mi][ni][hh * 2 + 1];
                    float h0v = g2.x / (1.f + expf(-g2.x)) * u0;
                    float h1v = g2.y / (1.f + expf(-g2.y)) * u1;
                    __half2 hv;
                    hv.x = __float2half(h0v);
                    hv.y = __float2half(h1v);
                    *(__half2*)(H + (size_t)(r0 + row) * D_FFN + h0 + col) = hv;
                }
    }
}

// ---------------- down GEMM: 128M x 128N, 3-stage ring ---------------------------
__global__ void __launch_bounds__(256, 2) mma_down_kernel() {
    const int by = blockIdx.y;
    const bool sh = (by < NT_SH);
    int te = 0, r0;
    if (sh) r0 = by * 128;
    else {
        int be = by - NT_SH;
        te = g_tile_dn[be];
        if (te < 0) return;
        r0 = be * 128;
    }
    const int slab = sh ? 0 : 1 + te;
    const int n0 = blockIdx.x * 128;
    const int tid = threadIdx.x, lane = tid & 31, wid = tid >> 5;
    const int wm = wid & 3, wn = wid >> 2;

    extern __shared__ __align__(16) char smem[];
    const uint32_t sbase = s2u(smem);

    const __half* __restrict__ Ah = sh ? g_Hs : g_He;
    const __half* __restrict__ B = g_Bd + (size_t)slab * D_MODEL * D_FFN;

    auto load_stage = [&](int s) {
        const int k0 = s << 5;
        const uint32_t st = sbase + (s % 3) * STG_B;
        {
            int row = tid >> 1, ch = tid & 1;
#pragma unroll
            for (int half = 0; half < 2; half++) {
                uint32_t off = row * 80 + (ch * 2 + half) * 16;
                cpa16(st + off,
                      Ah + (size_t)(r0 + row) * D_FFN + k0 + (ch * 2 + half) * 8);
                cpa16(st + TILE_B + off,
                      B + (size_t)(n0 + row) * D_FFN + k0 + (ch * 2 + half) * 8);
            }
        }
        cp_commit();
    };

    float acc[2][8][4];
#pragma unroll
    for (int i = 0; i < 2; i++)
#pragma unroll
        for (int j = 0; j < 8; j++)
#pragma unroll
            for (int q = 0; q < 4; q++) acc[i][j][q] = 0.f;

    load_stage(0); load_stage(1);
    for (int s = 0; s < DN_NSTG; s++) {
        cp_wait<1>();
        __syncthreads();
        if (s + 2 < DN_NSTG) load_stage(s + 2); else cp_commit();
        const uint32_t st = sbase + (s % 3) * STG_B;
        const int lr = lane & 15, lc = (lane >> 4) * 16;
#pragma unroll
        for (int kh = 0; kh < 2; kh++) {
            const int kb = kh * 32 + lc;
            uint32_t a[2][4];
#pragma unroll
            for (int mi = 0; mi < 2; mi++)
                ldm4(a[mi], st + (wm * 32 + mi * 16 + lr) * 80 + kb);
#pragma unroll
            for (int nj = 0; nj < 4; nj++) {
                uint32_t bf[4];
                ldm4(bf, st + TILE_B + (wn * 64 + nj * 16 + lr) * 80 + kb);
#pragma unroll
                for (int mi = 0; mi < 2; mi++) {
                    mma_f16(acc[mi][nj * 2],     a[mi], bf[0], bf[2]);
                    mma_f16(acc[mi][nj * 2 + 1], a[mi], bf[1], bf[3]);
                }
            }
        }
    }

    float* __restrict__ O = sh ? g_Os : g_Oe;
#pragma unroll
    for (int mi = 0; mi < 2; mi++)
#pragma unroll
        for (int ni = 0; ni < 8; ni++)
#pragma unroll
            for (int hh = 0; hh < 2; hh++) {
                int row = wm * 32 + mi * 16 + (lane >> 2) + hh * 8;
                int col = n0 + wn * 64 + ni * 8 + 2 * (lane & 3);
                float2 v; v.x = acc[mi][ni][hh * 2]; v.y = acc[mi][ni][hh * 2 + 1];
                *(float2*)(O + (size_t)(r0 + row) * D_MODEL + col) = v;
            }
}

// ---------------- combine: out = Os + w0*Oe[s0] + w1*Oe[s1] -----------------------
__global__ void combine_kernel(float* __restrict__ out) {
    int t = blockIdx.x;
    int tid = threadIdx.x;
    int s0 = g_tok_slot[t * 2 + 0], s1 = g_tok_slot[t * 2 + 1];
    float w0 = g_tok_w[t * 2 + 0],  w1 = g_tok_w[t * 2 + 1];
    const float4* a = (const float4*)(g_Os + (size_t)t * D_MODEL) + tid;
    const float4* b = (const float4*)(g_Oe + (size_t)s0 * D_MODEL) + tid;
    const float4* c = (const float4*)(g_Oe + (size_t)s1 * D_MODEL) + tid;
    float4 va = *a, vb = *b, vc = *c;
    float4 r;
    r.x = va.x + w0 * vb.x + w1 * vc.x;
    r.y = va.y + w0 * vb.y + w1 * vc.y;
    r.z = va.z + w0 * vb.z + w1 * vc.z;
    r.w = va.w + w0 * vb.w + w1 * vc.w;
    *((float4*)(out + (size_t)t * D_MODEL) + tid) = r;
}

// ---------------- launch ------------------------------------------------------------
extern "C" void kernel_launch(void* const* d_in, const int* in_sizes, int n_in,
                              void* d_out, int out_size) {
    const float* x         = (const float*)d_in[0];
    const float* shared_wg = (const float*)d_in[1];
    const float* shared_wu = (const float*)d_in[2];
    const float* shared_wd = (const float*)d_in[3];
    const float* exp_wg    = (const float*)d_in[4];
    const float* exp_wu    = (const float*)d_in[5];
    const float* exp_wd    = (const float*)d_in[6];
    const float* router_w  = (const float*)d_in[7];
    float* out = (float*)d_out;

    __half *bgu, *bd;
    cudaGetSymbolAddress((void**)&bgu, g_Bgu);
    cudaGetSymbolAddress((void**)&bd, g_Bd);

    cudaFuncSetAttribute(mma_gateup_kernel,
                         cudaFuncAttributeMaxDynamicSharedMemorySize, MM_SMEM);
    cudaFuncSetAttribute(mma_down_kernel,
                         cudaFuncAttributeMaxDynamicSharedMemorySize, MM_SMEM);

    init_kernel<<<(MAXSLOT + 255) / 256, 256>>>();
    router_kernel<<<N_TOK / 4, 128>>>(x, router_w);
    offsets_kernel<<<1, 128>>>(out, out_size);
    scatter_kernel<<<N_TOK / 256, 256>>>();

    conv_x_kernel<<<(N_TOK * D_MODEL) / 256, 256>>>(x);
    conv_gu_kernel<<<dim3(D_FFN / 32, D_MODEL / 32, 9), 256>>>(
        shared_wg, exp_wg, shared_wu, exp_wu, bgu);
    conv_w_kernel<<<dim3(D_MODEL / 32, D_FFN / 32, 9), 256>>>(
        shared_wd, exp_wd, bd, D_FFN, D_MODEL);

    mma_gateup_kernel<<<dim3(D_FFN / 64, NT_SH + NT_DN), 256, MM_SMEM>>>();
    mma_down_kernel<<<dim3(D_MODEL / 128, NT_SH + NT_DN), 256, MM_SMEM>>>();
    combine_kernel<<<N_TOK, 256>>>(out);
}

// round 15
// speedup vs baseline: 1.1626x; 1.0323x over previous
#include <cuda_runtime.h>
#include <cuda_fp16.h>
#include <math.h>
#include <stdint.h>

#define D_MODEL 1024
#define D_FFN   2048
#define N_TOK   4096
#define N_EXP   8
#define MAXSLOT 9216
#define NT_SH   (N_TOK / 128)     /* 32 shared row tiles */
#define NT_DN   (MAXSLOT / 128)   /* 72 expert row tiles */

#define TILE_B  10240             /* 128 rows * 80B (padded 64B row) */
#define STG_B   (2 * TILE_B)      /* A, B = 20480 */
#define DN_SMEM (2 * STG_B)       /* 40960, 2-stage ring */
#define GU_SMEM 53248             /* ring 40960; epilogue gbuf 33792 + hbuf 18432 */
#define GU_NSTG 32                /* K=1024 / 32 */
#define DN_NSTG 64                /* K=2048 / 32 */

// ---------------- scratch ----------------------------------------------------
__device__ __half g_Xh[(size_t)N_TOK * D_MODEL];
// gate+up interleaved: [slab][4096 n][1024 k]; n-chunk c (128 wide) = G cols
// [64c,64c+64) at +0..63, U cols [64c,64c+64) at +64..127
__device__ __half g_Bgu[(size_t)9 * 2 * D_FFN * D_MODEL];
__device__ __half g_Bd[(size_t)9 * D_MODEL * D_FFN];
__device__ __half g_Hs[(size_t)N_TOK * D_FFN];
__device__ __half g_He[(size_t)MAXSLOT * D_FFN];
__device__ float g_Os[(size_t)N_TOK * D_MODEL];
__device__ float g_Oe[(size_t)MAXSLOT * D_MODEL];
__device__ int   g_slot_token[MAXSLOT];
__device__ int   g_counts[N_EXP];
__device__ float g_psum[N_EXP];
__device__ int   g_fill[N_EXP];
__device__ int   g_padoff[N_EXP + 1];
__device__ int   g_tile_dn[NT_DN];
__device__ int   g_tok_idx[N_TOK * 2];
__device__ int   g_tok_slot[N_TOK * 2];
__device__ float g_tok_w[N_TOK * 2];

// ---------------- PTX helpers -------------------------------------------------
__device__ __forceinline__ uint32_t s2u(const void* p) {
    return (uint32_t)__cvta_generic_to_shared(p);
}
__device__ __forceinline__ void cpa16(uint32_t dst, const void* src) {
    asm volatile("cp.async.cg.shared.global [%0], [%1], 16;" :: "r"(dst), "l"(src));
}
__device__ __forceinline__ void cp_commit() {
    asm volatile("cp.async.commit_group;");
}
template <int N>
__device__ __forceinline__ void cp_wait() {
    asm volatile("cp.async.wait_group %0;" :: "n"(N));
}
__device__ __forceinline__ void ldm4(uint32_t* r, uint32_t addr) {
    asm volatile("ldmatrix.sync.aligned.m8n8.x4.shared.b16 {%0,%1,%2,%3}, [%4];"
                 : "=r"(r[0]), "=r"(r[1]), "=r"(r[2]), "=r"(r[3]) : "r"(addr));
}
__device__ __forceinline__ void mma_f16(float* c, const uint32_t* a,
                                        uint32_t b0, uint32_t b1) {
    asm volatile("mma.sync.aligned.m16n8k16.row.col.f32.f16.f16.f32 "
                 "{%0,%1,%2,%3}, {%4,%5,%6,%7}, {%8,%9}, {%0,%1,%2,%3};"
                 : "+f"(c[0]), "+f"(c[1]), "+f"(c[2]), "+f"(c[3])
                 : "r"(a[0]), "r"(a[1]), "r"(a[2]), "r"(a[3]), "r"(b0), "r"(b1));
}

// ---------------- routing kernels ---------------------------------------------
__global__ void init_kernel() {
    int i = blockIdx.x * blockDim.x + threadIdx.x;
    if (i < MAXSLOT) g_slot_token[i] = -1;
    if (i < N_EXP) { g_counts[i] = 0; g_psum[i] = 0.f; g_fill[i] = 0; }
}

__global__ void router_kernel(const float* __restrict__ x,
                              const float* __restrict__ rw) {
    int t = blockIdx.x * 4 + (threadIdx.x >> 5);
    int lane = threadIdx.x & 31;
    if (t >= N_TOK) return;
    const float* xr = x + (size_t)t * D_MODEL;
    float acc[N_EXP];
#pragma unroll
    for (int e = 0; e < N_EXP; e++) acc[e] = 0.f;
    for (int k = lane; k < D_MODEL; k += 32) {
        float xv = xr[k];
#pragma unroll
        for (int e = 0; e < N_EXP; e++) acc[e] += xv * rw[k * N_EXP + e];
    }
#pragma unroll
    for (int e = 0; e < N_EXP; e++)
#pragma unroll
        for (int o = 16; o; o >>= 1) acc[e] += __shfl_xor_sync(0xffffffffu, acc[e], o);
    if (lane == 0) {
        int i0 = 0; float v0 = acc[0];
#pragma unroll
        for (int e = 1; e < N_EXP; e++) if (acc[e] > v0) { v0 = acc[e]; i0 = e; }
        int i1 = -1; float v1 = -1e30f;
#pragma unroll
        for (int e = 0; e < N_EXP; e++) {
            if (e == i0) continue;
            if (acc[e] > v1) { v1 = acc[e]; i1 = e; }
        }
        float m2 = fmaxf(v0, v1);
        float e0 = expf(v0 - m2), e1 = expf(v1 - m2);
        float inv = 1.f / (e0 + e1);
        g_tok_idx[t * 2 + 0] = i0;  g_tok_w[t * 2 + 0] = e0 * inv;
        g_tok_idx[t * 2 + 1] = i1;  g_tok_w[t * 2 + 1] = e1 * inv;
        atomicAdd(&g_counts[i0], 1);
        atomicAdd(&g_counts[i1], 1);
        float mm = acc[0];
#pragma unroll
        for (int e = 1; e < N_EXP; e++) mm = fmaxf(mm, acc[e]);
        float s = 0.f, ex[N_EXP];
#pragma unroll
        for (int e = 0; e < N_EXP; e++) { ex[e] = expf(acc[e] - mm); s += ex[e]; }
        float invs = 1.f / s;
#pragma unroll
        for (int e = 0; e < N_EXP; e++) atomicAdd(&g_psum[e], ex[e] * invs);
    }
}

__global__ void offsets_kernel(float* __restrict__ out, int out_size) {
    __shared__ int spad[N_EXP + 1];
    int tid = threadIdx.x;
    if (tid == 0) {
        int off = 0;
        for (int e = 0; e < N_EXP; e++) {
            g_padoff[e] = off;
            off += ((g_counts[e] + 127) / 128) * 128;
        }
        g_padoff[N_EXP] = off;
        for (int e = 0; e <= N_EXP; e++) spad[e] = g_padoff[e];
        double s = 0.0;
        for (int e = 0; e < N_EXP; e++) s += (double)g_counts[e] * (double)g_psum[e];
        float aux = (float)((double)N_EXP * s / ((double)N_TOK * (double)N_TOK));
        if (out_size > N_TOK * D_MODEL) out[(size_t)N_TOK * D_MODEL] = aux;
    }
    __syncthreads();
    for (int j = tid; j < NT_DN; j += blockDim.x) {
        int row = j * 128, te = -1;
#pragma unroll
        for (int e = 0; e < N_EXP; e++)
            if (row >= spad[e] && row < spad[e + 1]) te = e;
        g_tile_dn[j] = te;
    }
}

__global__ void scatter_kernel() {
    int t = blockIdx.x * blockDim.x + threadIdx.x;
    if (t >= N_TOK) return;
#pragma unroll
    for (int k = 0; k < 2; k++) {
        int e = g_tok_idx[t * 2 + k];
        int pos = atomicAdd(&g_fill[e], 1);
        int slot = g_padoff[e] + pos;
        g_slot_token[slot] = t;
        g_tok_slot[t * 2 + k] = slot;
    }
}

// ---------------- conversions --------------------------------------------------
__global__ void conv_x_kernel(const float* __restrict__ x) {
    int i = (blockIdx.x * 256 + threadIdx.x) * 2;
    float2 v = *(const float2*)(x + i);
    __half2 h; h.x = __float2half(v.x); h.y = __float2half(v.y);
    *(__half2*)(g_Xh + i) = h;
}

// gate+up -> interleaved [slab][4096 n][1024 k] fp16; coalesced half2 writes.
// Tile: 64 k x 32 j, both G and U.
__global__ void conv_gu_kernel(const float* __restrict__ srcGs, const float* __restrict__ srcGe,
                               const float* __restrict__ srcUs, const float* __restrict__ srcUe,
                               __half* __restrict__ o) {
    int slab = blockIdx.z;
    const float* G = (slab == 0) ? srcGs : srcGe + (size_t)(slab - 1) * D_MODEL * D_FFN;
    const float* U = (slab == 0) ? srcUs : srcUe + (size_t)(slab - 1) * D_MODEL * D_FFN;
    size_t ob = (size_t)slab * 2 * D_FFN * D_MODEL;
    __shared__ __half tg[64][34], tu[64][34];
    int tid = threadIdx.x;
    int tx = tid & 31, ty = tid >> 5;
    int k0 = blockIdx.y * 64, j0 = blockIdx.x * 32;
#pragma unroll
    for (int p = 0; p < 8; p++) {
        int row = p * 8 + ty;
        size_t so = (size_t)(k0 + row) * D_FFN + j0 + tx;
        tg[row][tx] = __float2half(G[so]);
        tu[row][tx] = __float2half(U[so]);
    }
    __syncthreads();
    int nG0 = ((j0 >> 6) << 7) + (j0 & 63);
    int pk = tx;                       // k-pair index 0..31
#pragma unroll
    for (int pass = 0; pass < 4; pass++) {
        int jj = pass * 8 + ty;
        __half2 vg; vg.x = tg[2 * pk][jj]; vg.y = tg[2 * pk + 1][jj];
        __half2 vu; vu.x = tu[2 * pk][jj]; vu.y = tu[2 * pk + 1][jj];
        *(__half2*)(o + ob + (size_t)(nG0 + jj) * D_MODEL + k0 + 2 * pk) = vg;
        *(__half2*)(o + ob + (size_t)(nG0 + 64 + jj) * D_MODEL + k0 + 2 * pk) = vu;
    }
}

// down: transpose [R,C] fp32 -> [slab][C][R] fp16; coalesced half2 writes.
__global__ void conv_w_kernel(const float* __restrict__ srcS, const float* __restrict__ srcE,
                              __half* __restrict__ o, int R, int C) {
    int slab = blockIdx.z;
    const float* src = (slab == 0) ? srcS : srcE + (size_t)(slab - 1) * R * C;
    size_t ob = (size_t)slab * R * C;
    __shared__ __half t[64][34];
    int tid = threadIdx.x;
    int tx = tid & 31, ty = tid >> 5;
    int r0 = blockIdx.y * 64, c0 = blockIdx.x * 32;
#pragma unroll
    for (int p = 0; p < 8; p++) {
        int row = p * 8 + ty;
        t[row][tx] = __float2half(src[(size_t)(r0 + row) * C + c0 + tx]);
    }
    __syncthreads();
    int pk = tx;
#pragma unroll
    for (int pass = 0; pass < 4; pass++) {
        int jj = pass * 8 + ty;
        __half2 v; v.x = t[2 * pk][jj]; v.y = t[2 * pk + 1][jj];
        *(__half2*)(o + ob + (size_t)(c0 + jj) * R + r0 + 2 * pk) = v;
    }
}

// ---------------- gate+up GEMM: 128M x 128N(=64G+64U), 2-stage ring -------------
__global__ void __launch_bounds__(256, 2) mma_gateup_kernel() {
    const int by = blockIdx.y;
    const bool sh = (by < NT_SH);
    int te = 0, r0;
    if (sh) r0 = by * 128;
    else {
        int be = by - NT_SH;
        te = g_tile_dn[be];
        if (te < 0) return;
        r0 = be * 128;
    }
    const int slab = sh ? 0 : 1 + te;
    const int n0b = blockIdx.x * 128;        // interleaved B row base
    const int h0 = blockIdx.x * 64;          // H column base
    const int tid = threadIdx.x, lane = tid & 31, wid = tid >> 5;
    const int wm = wid & 3, wn = wid >> 2;

    extern __shared__ __align__(16) char smem[];
    __shared__ int stok[128];
    const uint32_t sbase = s2u(smem);

    if (tid < 128) {
        if (sh) stok[tid] = r0 + tid;
        else { int t = g_slot_token[r0 + tid]; stok[tid] = t < 0 ? 0 : t; }
    }
    __syncthreads();

    const __half* __restrict__ B = g_Bgu + (size_t)slab * 2 * D_FFN * D_MODEL;

    auto load_stage = [&](int s) {
        const int k0 = s << 5;
        const uint32_t st = sbase + (s & 1) * STG_B;
        {
            int row = tid >> 1, ch = tid & 1;
#pragma unroll
            for (int half = 0; half < 2; half++) {
                uint32_t off = row * 80 + (ch * 2 + half) * 16;
                cpa16(st + off,
                      g_Xh + (size_t)stok[row] * D_MODEL + k0 + (ch * 2 + half) * 8);
                cpa16(st + TILE_B + off,
                      B + (size_t)(n0b + row) * D_MODEL + k0 + (ch * 2 + half) * 8);
            }
        }
        cp_commit();
    };

    float acc[2][8][4];
#pragma unroll
    for (int i = 0; i < 2; i++)
#pragma unroll
        for (int j = 0; j < 8; j++)
#pragma unroll
            for (int q = 0; q < 4; q++) acc[i][j][q] = 0.f;

    load_stage(0);
    for (int s = 0; s < GU_NSTG; s++) {
        cp_wait<0>();
        __syncthreads();
        if (s + 1 < GU_NSTG) load_stage(s + 1);
        const uint32_t st = sbase + (s & 1) * STG_B;
        const int lr = lane & 15, lc = (lane >> 4) * 16;
#pragma unroll
        for (int kh = 0; kh < 2; kh++) {
            const int kb = kh * 32 + lc;
            uint32_t a[2][4];
#pragma unroll
            for (int mi = 0; mi < 2; mi++)
                ldm4(a[mi], st + (wm * 32 + mi * 16 + lr) * 80 + kb);
#pragma unroll
            for (int nj = 0; nj < 4; nj++) {
                uint32_t bf[4];
                ldm4(bf, st + TILE_B + (wn * 64 + nj * 16 + lr) * 80 + kb);
#pragma unroll
                for (int mi = 0; mi < 2; mi++) {
                    mma_f16(acc[mi][nj * 2],     a[mi], bf[0], bf[2]);
                    mma_f16(acc[mi][nj * 2 + 1], a[mi], bf[1], bf[3]);
                }
            }
        }
    }

    // SwiGLU epilogue: G warps (wn=0) -> gbuf (fp32), U warps compute H -> hbuf
    // (half, padded rows), then all threads store H with coalesced 16B writes.
    __syncthreads();
    float* gbuf = (float*)smem;                        // [128][66] fp32
    __half* hbuf = (__half*)(smem + 33792);            // [128][72] half
    if (wn == 0) {
#pragma unroll
        for (int mi = 0; mi < 2; mi++)
#pragma unroll
            for (int ni = 0; ni < 8; ni++)
#pragma unroll
                for (int hh = 0; hh < 2; hh++) {
                    int row = wm * 32 + mi * 16 + (lane >> 2) + hh * 8;
                    int col = ni * 8 + 2 * (lane & 3);
                    float2 v; v.x = acc[mi][ni][hh * 2]; v.y = acc[mi][ni][hh * 2 + 1];
                    *(float2*)(gbuf + row * 66 + col) = v;
                }
    }
    __syncthreads();
    if (wn == 1) {
#pragma unroll
        for (int mi = 0; mi < 2; mi++)
#pragma unroll
            for (int ni = 0; ni < 8; ni++)
#pragma unroll
                for (int hh = 0; hh < 2; hh++) {
                    int row = wm * 32 + mi * 16 + (lane >> 2) + hh * 8;
                    int col = ni * 8 + 2 * (lane & 3);
                    float2 g2 = *(const float2*)(gbuf + row * 66 + col);
                    float u0 = acc[mi][ni][hh * 2], u1 = acc[mi][ni][hh * 2 + 1];
                    float h0v = g2.x / (1.f + expf(-g2.x)) * u0;
                    float h1v = g2.y / (1.f + expf(-g2.y)) * u1;
                    __half2 hv;
                    hv.x = __float2half(h0v);
                    hv.y = __float2half(h1v);
                    *(__half2*)(hbuf + row * 72 + col) = hv;
                }
    }
    __syncthreads();
    {
        __half* __restrict__ H = sh ? g_Hs : g_He;
        int row8 = tid >> 3, c16 = (tid & 7) * 8;
#pragma unroll
        for (int it = 0; it < 4; it++) {
            int row = it * 32 + row8;
            uint4 v = *(const uint4*)(hbuf + row * 72 + c16);
            *(uint4*)(H + (size_t)(r0 + row) * D_FFN + h0 + c16) = v;
        }
    }
}

// ---------------- down GEMM: 128M x 128N, 2-stage ring ---------------------------
__global__ void __launch_bounds__(256, 2) mma_down_kernel() {
    const int by = blockIdx.y;
    const bool sh = (by < NT_SH);
    int te = 0, r0;
    if (sh) r0 = by * 128;
    else {
        int be = by - NT_SH;
        te = g_tile_dn[be];
        if (te < 0) return;
        r0 = be * 128;
    }
    const int slab = sh ? 0 : 1 + te;
    const int n0 = blockIdx.x * 128;
    const int tid = threadIdx.x, lane = tid & 31, wid = tid >> 5;
    const int wm = wid & 3, wn = wid >> 2;

    extern __shared__ __align__(16) char smem[];
    const uint32_t sbase = s2u(smem);

    const __half* __restrict__ Ah = sh ? g_Hs : g_He;
    const __half* __restrict__ B = g_Bd + (size_t)slab * D_MODEL * D_FFN;

    auto load_stage = [&](int s) {
        const int k0 = s << 5;
        const uint32_t st = sbase + (s & 1) * STG_B;
        {
            int row = tid >> 1, ch = tid & 1;
#pragma unroll
            for (int half = 0; half < 2; half++) {
                uint32_t off = row * 80 + (ch * 2 + half) * 16;
                cpa16(st + off,
                      Ah + (size_t)(r0 + row) * D_FFN + k0 + (ch * 2 + half) * 8);
                cpa16(st + TILE_B + off,
                      B + (size_t)(n0 + row) * D_FFN + k0 + (ch * 2 + half) * 8);
            }
        }
        cp_commit();
    };

    float acc[2][8][4];
#pragma unroll
    for (int i = 0; i < 2; i++)
#pragma unroll
        for (int j = 0; j < 8; j++)
#pragma unroll
            for (int q = 0; q < 4; q++) acc[i][j][q] = 0.f;

    load_stage(0);
    for (int s = 0; s < DN_NSTG; s++) {
        cp_wait<0>();
        __syncthreads();
        if (s + 1 < DN_NSTG) load_stage(s + 1);
        const uint32_t st = sbase + (s & 1) * STG_B;
        const int lr = lane & 15, lc = (lane >> 4) * 16;
#pragma unroll
        for (int kh = 0; kh < 2; kh++) {
            const int kb = kh * 32 + lc;
            uint32_t a[2][4];
#pragma unroll
            for (int mi = 0; mi < 2; mi++)
                ldm4(a[mi], st + (wm * 32 + mi * 16 + lr) * 80 + kb);
#pragma unroll
            for (int nj = 0; nj < 4; nj++) {
                uint32_t bf[4];
                ldm4(bf, st + TILE_B + (wn * 64 + nj * 16 + lr) * 80 + kb);
#pragma unroll
                for (int mi = 0; mi < 2; mi++) {
                    mma_f16(acc[mi][nj * 2],     a[mi], bf[0], bf[2]);
                    mma_f16(acc[mi][nj * 2 + 1], a[mi], bf[1], bf[3]);
                }
            }
        }
    }

    float* __restrict__ O = sh ? g_Os : g_Oe;
#pragma unroll
    for (int mi = 0; mi < 2; mi++)
#pragma unroll
        for (int ni = 0; ni < 8; ni++)
#pragma unroll
            for (int hh = 0; hh < 2; hh++) {
                int row = wm * 32 + mi * 16 + (lane >> 2) + hh * 8;
                int col = n0 + wn * 64 + ni * 8 + 2 * (lane & 3);
                float2 v; v.x = acc[mi][ni][hh * 2]; v.y = acc[mi][ni][hh * 2 + 1];
                *(float2*)(O + (size_t)(r0 + row) * D_MODEL + col) = v;
            }
}

// ---------------- combine: out = Os + w0*Oe[s0] + w1*Oe[s1] -----------------------
__global__ void combine_kernel(float* __restrict__ out) {
    int t = blockIdx.x;
    int tid = threadIdx.x;
    int s0 = g_tok_slot[t * 2 + 0], s1 = g_tok_slot[t * 2 + 1];
    float w0 = g_tok_w[t * 2 + 0],  w1 = g_tok_w[t * 2 + 1];
    const float4* a = (const float4*)(g_Os + (size_t)t * D_MODEL) + tid;
    const float4* b = (const float4*)(g_Oe + (size_t)s0 * D_MODEL) + tid;
    const float4* c = (const float4*)(g_Oe + (size_t)s1 * D_MODEL) + tid;
    float4 va = *a, vb = *b, vc = *c;
    float4 r;
    r.x = va.x + w0 * vb.x + w1 * vc.x;
    r.y = va.y + w0 * vb.y + w1 * vc.y;
    r.z = va.z + w0 * vb.z + w1 * vc.z;
    r.w = va.w + w0 * vb.w + w1 * vc.w;
    *((float4*)(out + (size_t)t * D_MODEL) + tid) = r;
}

// ---------------- launch ------------------------------------------------------------
extern "C" void kernel_launch(void* const* d_in, const int* in_sizes, int n_in,
                              void* d_out, int out_size) {
    const float* x         = (const float*)d_in[0];
    const float* shared_wg = (const float*)d_in[1];
    const float* shared_wu = (const float*)d_in[2];
    const float* shared_wd = (const float*)d_in[3];
    const float* exp_wg    = (const float*)d_in[4];
    const float* exp_wu    = (const float*)d_in[5];
    const float* exp_wd    = (const float*)d_in[6];
    const float* router_w  = (const float*)d_in[7];
    float* out = (float*)d_out;

    __half *bgu, *bd;
    cudaGetSymbolAddress((void**)&bgu, g_Bgu);
    cudaGetSymbolAddress((void**)&bd, g_Bd);

    cudaFuncSetAttribute(mma_gateup_kernel,
                         cudaFuncAttributeMaxDynamicSharedMemorySize, GU_SMEM);
    cudaFuncSetAttribute(mma_down_kernel,
                         cudaFuncAttributeMaxDynamicSharedMemorySize, DN_SMEM);

    init_kernel<<<(MAXSLOT + 255) / 256, 256>>>();
    router_kernel<<<N_TOK / 4, 128>>>(x, router_w);
    offsets_kernel<<<1, 128>>>(out, out_size);
    scatter_kernel<<<N_TOK / 256, 256>>>();

    conv_x_kernel<<<(N_TOK * D_MODEL) / 512, 256>>>(x);
    conv_gu_kernel<<<dim3(D_FFN / 32, D_MODEL / 64, 9), 256>>>(
        shared_wg, exp_wg, shared_wu, exp_wu, bgu);
    conv_w_kernel<<<dim3(D_MODEL / 32, D_FFN / 64, 9), 256>>>(
        shared_wd, exp_wd, bd, D_FFN, D_MODEL);

    mma_gateup_kernel<<<dim3(D_FFN / 64, NT_SH + NT_DN), 256, GU_SMEM>>>();
    mma_down_kernel<<<dim3(D_MODEL / 128, NT_SH + NT_DN), 256, DN_SMEM>>>();
    combine_kernel<<<N_TOK, 256>>>(out);
}

// round 16
// speedup vs baseline: 1.1786x; 1.0137x over previous
#include <cuda_runtime.h>
#include <cuda_fp16.h>
#include <math.h>
#include <stdint.h>

#define D_MODEL 1024
#define D_FFN   2048
#define N_TOK   4096
#define N_EXP   8
#define MAXSLOT 9216
#define NT_SH   (N_TOK / 128)     /* 32 shared row tiles */
#define NT_DN   (MAXSLOT / 128)   /* 72 expert row tiles */

#define TILE_A  10240             /* 128 rows * 80B */
#define TILE_BB 5120              /* 64 rows * 80B  */
#define STG_B   (TILE_A + TILE_BB)/* 15360 */
#define MM_SMEM (2 * STG_B)       /* 30720, 2-stage ring */
#define GU_NSTG 32                /* K=1024 / 32 */
#define DN_NSTG 64                /* K=2048 / 32 */

// ---------------- scratch ----------------------------------------------------
__device__ __half g_Xh[(size_t)N_TOK * D_MODEL];
// gate+up interleaved: [slab][4096 n][1024 k]; 64-chunk c: G cols [32c,32c+32)
// at +0..31, U cols [32c,32c+32) at +32..63
__device__ __half g_Bgu[(size_t)9 * 2 * D_FFN * D_MODEL];
__device__ __half g_Bd[(size_t)9 * D_MODEL * D_FFN];
__device__ __half g_Hs[(size_t)N_TOK * D_FFN];
__device__ __half g_He[(size_t)MAXSLOT * D_FFN];
__device__ float g_Os[(size_t)N_TOK * D_MODEL];
__device__ float g_Oe[(size_t)MAXSLOT * D_MODEL];
__device__ int   g_slot_token[MAXSLOT];
__device__ int   g_counts[N_EXP];
__device__ float g_psum[N_EXP];
__device__ int   g_fill[N_EXP];
__device__ int   g_padoff[N_EXP + 1];
__device__ int   g_tile_dn[NT_DN];
__device__ int   g_tok_idx[N_TOK * 2];
__device__ int   g_tok_slot[N_TOK * 2];
__device__ float g_tok_w[N_TOK * 2];

// ---------------- PTX helpers -------------------------------------------------
__device__ __forceinline__ uint32_t s2u(const void* p) {
    return (uint32_t)__cvta_generic_to_shared(p);
}
__device__ __forceinline__ void cpa16(uint32_t dst, const void* src) {
    asm volatile("cp.async.cg.shared.global [%0], [%1], 16;" :: "r"(dst), "l"(src));
}
__device__ __forceinline__ void cp_commit() {
    asm volatile("cp.async.commit_group;");
}
template <int N>
__device__ __forceinline__ void cp_wait() {
    asm volatile("cp.async.wait_group %0;" :: "n"(N));
}
__device__ __forceinline__ void ldm4(uint32_t* r, uint32_t addr) {
    asm volatile("ldmatrix.sync.aligned.m8n8.x4.shared.b16 {%0,%1,%2,%3}, [%4];"
                 : "=r"(r[0]), "=r"(r[1]), "=r"(r[2]), "=r"(r[3]) : "r"(addr));
}
__device__ __forceinline__ void mma_f16(float* c, const uint32_t* a,
                                        uint32_t b0, uint32_t b1) {
    asm volatile("mma.sync.aligned.m16n8k16.row.col.f32.f16.f16.f32 "
                 "{%0,%1,%2,%3}, {%4,%5,%6,%7}, {%8,%9}, {%0,%1,%2,%3};"
                 : "+f"(c[0]), "+f"(c[1]), "+f"(c[2]), "+f"(c[3])
                 : "r"(a[0]), "r"(a[1]), "r"(a[2]), "r"(a[3]), "r"(b0), "r"(b1));
}

// ---------------- routing kernels ---------------------------------------------
__global__ void init_kernel() {
    int i = blockIdx.x * blockDim.x + threadIdx.x;
    if (i < MAXSLOT) g_slot_token[i] = -1;
    if (i < N_EXP) { g_counts[i] = 0; g_psum[i] = 0.f; g_fill[i] = 0; }
}

__global__ void router_kernel(const float* __restrict__ x,
                              const float* __restrict__ rw) {
    int t = blockIdx.x * 4 + (threadIdx.x >> 5);
    int lane = threadIdx.x & 31;
    if (t >= N_TOK) return;
    const float* xr = x + (size_t)t * D_MODEL;
    float acc[N_EXP];
#pragma unroll
    for (int e = 0; e < N_EXP; e++) acc[e] = 0.f;
    for (int k = lane; k < D_MODEL; k += 32) {
        float xv = xr[k];
#pragma unroll
        for (int e = 0; e < N_EXP; e++) acc[e] += xv * rw[k * N_EXP + e];
    }
#pragma unroll
    for (int e = 0; e < N_EXP; e++)
#pragma unroll
        for (int o = 16; o; o >>= 1) acc[e] += __shfl_xor_sync(0xffffffffu, acc[e], o);
    if (lane == 0) {
        int i0 = 0; float v0 = acc[0];
#pragma unroll
        for (int e = 1; e < N_EXP; e++) if (acc[e] > v0) { v0 = acc[e]; i0 = e; }
        int i1 = -1; float v1 = -1e30f;
#pragma unroll
        for (int e = 0; e < N_EXP; e++) {
            if (e == i0) continue;
            if (acc[e] > v1) { v1 = acc[e]; i1 = e; }
        }
        float m2 = fmaxf(v0, v1);
        float e0 = expf(v0 - m2), e1 = expf(v1 - m2);
        float inv = 1.f / (e0 + e1);
        g_tok_idx[t * 2 + 0] = i0;  g_tok_w[t * 2 + 0] = e0 * inv;
        g_tok_idx[t * 2 + 1] = i1;  g_tok_w[t * 2 + 1] = e1 * inv;
        atomicAdd(&g_counts[i0], 1);
        atomicAdd(&g_counts[i1], 1);
        float mm = acc[0];
#pragma unroll
        for (int e = 1; e < N_EXP; e++) mm = fmaxf(mm, acc[e]);
        float s = 0.f, ex[N_EXP];
#pragma unroll
        for (int e = 0; e < N_EXP; e++) { ex[e] = expf(acc[e] - mm); s += ex[e]; }
        float invs = 1.f / s;
#pragma unroll
        for (int e = 0; e < N_EXP; e++) atomicAdd(&g_psum[e], ex[e] * invs);
    }
}

__global__ void offsets_kernel(float* __restrict__ out, int out_size) {
    __shared__ int spad[N_EXP + 1];
    int tid = threadIdx.x;
    if (tid == 0) {
        int off = 0;
        for (int e = 0; e < N_EXP; e++) {
            g_padoff[e] = off;
            off += ((g_counts[e] + 127) / 128) * 128;
        }
        g_padoff[N_EXP] = off;
        for (int e = 0; e <= N_EXP; e++) spad[e] = g_padoff[e];
        double s = 0.0;
        for (int e = 0; e < N_EXP; e++) s += (double)g_counts[e] * (double)g_psum[e];
        float aux = (float)((double)N_EXP * s / ((double)N_TOK * (double)N_TOK));
        if (out_size > N_TOK * D_MODEL) out[(size_t)N_TOK * D_MODEL] = aux;
    }
    __syncthreads();
    for (int j = tid; j < NT_DN; j += blockDim.x) {
        int row = j * 128, te = -1;
#pragma unroll
        for (int e = 0; e < N_EXP; e++)
            if (row >= spad[e] && row < spad[e + 1]) te = e;
        g_tile_dn[j] = te;
    }
}

__global__ void scatter_kernel() {
    int t = blockIdx.x * blockDim.x + threadIdx.x;
    if (t >= N_TOK) return;
#pragma unroll
    for (int k = 0; k < 2; k++) {
        int e = g_tok_idx[t * 2 + k];
        int pos = atomicAdd(&g_fill[e], 1);
        int slot = g_padoff[e] + pos;
        g_slot_token[slot] = t;
        g_tok_slot[t * 2 + k] = slot;
    }
}

// ---------------- conversions --------------------------------------------------
__global__ void conv_x_kernel(const float* __restrict__ x) {
    int i = (blockIdx.x * 256 + threadIdx.x) * 2;
    float2 v = *(const float2*)(x + i);
    __half2 h; h.x = __float2half(v.x); h.y = __float2half(v.y);
    *(__half2*)(g_Xh + i) = h;
}

// gate+up -> interleaved [slab][4096 n][1024 k] fp16, 64-row chunks (32G+32U)
__global__ void conv_gu_kernel(const float* __restrict__ srcGs, const float* __restrict__ srcGe,
                               const float* __restrict__ srcUs, const float* __restrict__ srcUe,
                               __half* __restrict__ o) {
    int slab = blockIdx.z;
    const float* G = (slab == 0) ? srcGs : srcGe + (size_t)(slab - 1) * D_MODEL * D_FFN;
    const float* U = (slab == 0) ? srcUs : srcUe + (size_t)(slab - 1) * D_MODEL * D_FFN;
    size_t ob = (size_t)slab * 2 * D_FFN * D_MODEL;
    __shared__ __half tg[64][34], tu[64][34];
    int tid = threadIdx.x;
    int tx = tid & 31, ty = tid >> 5;
    int k0 = blockIdx.y * 64, j0 = blockIdx.x * 32;
#pragma unroll
    for (int p = 0; p < 8; p++) {
        int row = p * 8 + ty;
        size_t so = (size_t)(k0 + row) * D_FFN + j0 + tx;
        tg[row][tx] = __float2half(G[so]);
        tu[row][tx] = __float2half(U[so]);
    }
    __syncthreads();
    int nG0 = 2 * j0;                  // 64-chunk interleave: G at +0..31, U at +32..63
    int pk = tx;
#pragma unroll
    for (int pass = 0; pass < 4; pass++) {
        int jj = pass * 8 + ty;
        __half2 vg; vg.x = tg[2 * pk][jj]; vg.y = tg[2 * pk + 1][jj];
        __half2 vu; vu.x = tu[2 * pk][jj]; vu.y = tu[2 * pk + 1][jj];
        *(__half2*)(o + ob + (size_t)(nG0 + jj) * D_MODEL + k0 + 2 * pk) = vg;
        *(__half2*)(o + ob + (size_t)(nG0 + 32 + jj) * D_MODEL + k0 + 2 * pk) = vu;
    }
}

// down: transpose [R,C] fp32 -> [slab][C][R] fp16
__global__ void conv_w_kernel(const float* __restrict__ srcS, const float* __restrict__ srcE,
                              __half* __restrict__ o, int R, int C) {
    int slab = blockIdx.z;
    const float* src = (slab == 0) ? srcS : srcE + (size_t)(slab - 1) * R * C;
    size_t ob = (size_t)slab * R * C;
    __shared__ __half t[64][34];
    int tid = threadIdx.x;
    int tx = tid & 31, ty = tid >> 5;
    int r0 = blockIdx.y * 64, c0 = blockIdx.x * 32;
#pragma unroll
    for (int p = 0; p < 8; p++) {
        int row = p * 8 + ty;
        t[row][tx] = __float2half(src[(size_t)(r0 + row) * C + c0 + tx]);
    }
    __syncthreads();
    int pk = tx;
#pragma unroll
    for (int pass = 0; pass < 4; pass++) {
        int jj = pass * 8 + ty;
        __half2 v; v.x = t[2 * pk][jj]; v.y = t[2 * pk + 1][jj];
        *(__half2*)(o + ob + (size_t)(c0 + jj) * R + r0 + 2 * pk) = v;
    }
}

// ---------------- gate+up GEMM: 128M x 64N(=32G+32U), 128 thr, 4 CTA/SM ---------
__global__ void __launch_bounds__(128, 4) mma_gateup_kernel() {
    const int by = blockIdx.y;
    const bool sh = (by < NT_SH);
    int te = 0, r0;
    if (sh) r0 = by * 128;
    else {
        int be = by - NT_SH;
        te = g_tile_dn[be];
        if (te < 0) return;
        r0 = be * 128;
    }
    const int slab = sh ? 0 : 1 + te;
    const int n0b = blockIdx.x * 64;         // interleaved B row base
    const int h0 = blockIdx.x * 32;          // H column base
    const int tid = threadIdx.x, lane = tid & 31, wid = tid >> 5;
    const int wm = wid & 1, wn = wid >> 1;   // wn: 0 = G warps, 1 = U warps

    extern __shared__ __align__(16) char smem[];
    __shared__ int stok[128];
    const uint32_t sbase = s2u(smem);

    if (sh) stok[tid] = r0 + tid;
    else { int t = g_slot_token[r0 + tid]; stok[tid] = t < 0 ? 0 : t; }
    __syncthreads();

    const __half* __restrict__ B = g_Bgu + (size_t)slab * 2 * D_FFN * D_MODEL;

    auto load_stage = [&](int s) {
        const int k0 = s << 5;
        const uint32_t st = sbase + (s & 1) * STG_B;
#pragma unroll
        for (int it = 0; it < 4; it++) {         // A: 512 cpa16
            int idx = tid + it * 128;
            int row = idx >> 2, ch = idx & 3;
            cpa16(st + row * 80 + ch * 16,
                  g_Xh + (size_t)stok[row] * D_MODEL + k0 + ch * 8);
        }
#pragma unroll
        for (int it = 0; it < 2; it++) {         // B: 256 cpa16
            int idx = tid + it * 128;
            int row = idx >> 2, ch = idx & 3;
            cpa16(st + TILE_A + row * 80 + ch * 16,
                  B + (size_t)(n0b + row) * D_MODEL + k0 + ch * 8);
        }
        cp_commit();
    };

    float acc[4][4][4];
#pragma unroll
    for (int i = 0; i < 4; i++)
#pragma unroll
        for (int j = 0; j < 4; j++)
#pragma unroll
            for (int q = 0; q < 4; q++) acc[i][j][q] = 0.f;

    load_stage(0);
    for (int s = 0; s < GU_NSTG; s++) {
        cp_wait<0>();
        __syncthreads();
        if (s + 1 < GU_NSTG) load_stage(s + 1);
        const uint32_t st = sbase + (s & 1) * STG_B;
        const int lr = lane & 15, lc = (lane >> 4) * 16;
#pragma unroll
        for (int kh = 0; kh < 2; kh++) {
            const int kb = kh * 32 + lc;
            uint32_t a[4][4];
#pragma unroll
            for (int mi = 0; mi < 4; mi++)
                ldm4(a[mi], st + (wm * 64 + mi * 16 + lr) * 80 + kb);
#pragma unroll
            for (int nj2 = 0; nj2 < 2; nj2++) {
                uint32_t bf[4];
                ldm4(bf, st + TILE_A + (wn * 32 + nj2 * 16 + lr) * 80 + kb);
#pragma unroll
                for (int mi = 0; mi < 4; mi++) {
                    mma_f16(acc[mi][nj2 * 2],     a[mi], bf[0], bf[2]);
                    mma_f16(acc[mi][nj2 * 2 + 1], a[mi], bf[1], bf[3]);
                }
            }
        }
    }

    // SwiGLU epilogue: G warps (wn=0) -> gbuf fp32; U warps compute H -> hbuf;
    // then all threads store coalesced.
    __syncthreads();
    float* gbuf = (float*)smem;                 // [128][34] fp32 = 17408 B
    __half* hbuf = (__half*)(smem + 17408);     // [128][40] half = 10240 B
    if (wn == 0) {
#pragma unroll
        for (int mi = 0; mi < 4; mi++)
#pragma unroll
            for (int nj = 0; nj < 4; nj++)
#pragma unroll
                for (int hh = 0; hh < 2; hh++) {
                    int row = wm * 64 + mi * 16 + (lane >> 2) + hh * 8;
                    int col = nj * 8 + 2 * (lane & 3);
                    float2 v; v.x = acc[mi][nj][hh * 2]; v.y = acc[mi][nj][hh * 2 + 1];
                    *(float2*)(gbuf + row * 34 + col) = v;
                }
    }
    __syncthreads();
    if (wn == 1) {
#pragma unroll
        for (int mi = 0; mi < 4; mi++)
#pragma unroll
            for (int nj = 0; nj < 4; nj++)
#pragma unroll
                for (int hh = 0; hh < 2; hh++) {
                    int row = wm * 64 + mi * 16 + (lane >> 2) + hh * 8;
                    int col = nj * 8 + 2 * (lane & 3);
                    float2 g2 = *(const float2*)(gbuf + row * 34 + col);
                    float u0 = acc[mi][nj][hh * 2], u1 = acc[mi][nj][hh * 2 + 1];
                    float h0v = g2.x / (1.f + expf(-g2.x)) * u0;
                    float h1v = g2.y / (1.f + expf(-g2.y)) * u1;
                    __half2 hv;
                    hv.x = __float2half(h0v);
                    hv.y = __float2half(h1v);
                    *(__half2*)(hbuf + row * 40 + col) = hv;
                }
    }
    __syncthreads();
    {
        __half* __restrict__ H = sh ? g_Hs : g_He;
#pragma unroll
        for (int it = 0; it < 4; it++) {
            int idx = tid + it * 128;
            int row = idx >> 2, q = idx & 3;
            uint4 v = *(const uint4*)(hbuf + row * 40 + q * 8);
            *(uint4*)(H + (size_t)(r0 + row) * D_FFN + h0 + q * 8) = v;
        }
    }
}

// ---------------- down GEMM: 128M x 64N, 128 thr, 4 CTA/SM -----------------------
__global__ void __launch_bounds__(128, 4) mma_down_kernel() {
    const int by = blockIdx.y;
    const bool sh = (by < NT_SH);
    int te = 0, r0;
    if (sh) r0 = by * 128;
    else {
        int be = by - NT_SH;
        te = g_tile_dn[be];
        if (te < 0) return;
        r0 = be * 128;
    }
    const int slab = sh ? 0 : 1 + te;
    const int n0 = blockIdx.x * 64;
    const int tid = threadIdx.x, lane = tid & 31, wid = tid >> 5;
    const int wm = wid & 1, wn = wid >> 1;

    extern __shared__ __align__(16) char smem[];
    const uint32_t sbase = s2u(smem);

    const __half* __restrict__ Ah = sh ? g_Hs : g_He;
    const __half* __restrict__ B = g_Bd + (size_t)slab * D_MODEL * D_FFN;

    auto load_stage = [&](int s) {
        const int k0 = s << 5;
        const uint32_t st = sbase + (s & 1) * STG_B;
#pragma unroll
        for (int it = 0; it < 4; it++) {
            int idx = tid + it * 128;
            int row = idx >> 2, ch = idx & 3;
            cpa16(st + row * 80 + ch * 16,
                  Ah + (size_t)(r0 + row) * D_FFN + k0 + ch * 8);
        }
#pragma unroll
        for (int it = 0; it < 2; it++) {
            int idx = tid + it * 128;
            int row = idx >> 2, ch = idx & 3;
            cpa16(st + TILE_A + row * 80 + ch * 16,
                  B + (size_t)(n0 + row) * D_FFN + k0 + ch * 8);
        }
        cp_commit();
    };

    float acc[4][4][4];
#pragma unroll
    for (int i = 0; i < 4; i++)
#pragma unroll
        for (int j = 0; j < 4; j++)
#pragma unroll
            for (int q = 0; q < 4; q++) acc[i][j][q] = 0.f;

    load_stage(0);
    for (int s = 0; s < DN_NSTG; s++) {
        cp_wait<0>();
        __syncthreads();
        if (s + 1 < DN_NSTG) load_stage(s + 1);
        const uint32_t st = sbase + (s & 1) * STG_B;
        const int lr = lane & 15, lc = (lane >> 4) * 16;
#pragma unroll
        for (int kh = 0; kh < 2; kh++) {
            const int kb = kh * 32 + lc;
            uint32_t a[4][4];
#pragma unroll
            for (int mi = 0; mi < 4; mi++)
                ldm4(a[mi], st + (wm * 64 + mi * 16 + lr) * 80 + kb);
#pragma unroll
            for (int nj2 = 0; nj2 < 2; nj2++) {
                uint32_t bf[4];
                ldm4(bf, st + TILE_A + (wn * 32 + nj2 * 16 + lr) * 80 + kb);
#pragma unroll
                for (int mi = 0; mi < 4; mi++) {
                    mma_f16(acc[mi][nj2 * 2],     a[mi], bf[0], bf[2]);
                    mma_f16(acc[mi][nj2 * 2 + 1], a[mi], bf[1], bf[3]);
                }
            }
        }
    }

    float* __restrict__ O = sh ? g_Os : g_Oe;
#pragma unroll
    for (int mi = 0; mi < 4; mi++)
#pragma unroll
        for (int nj = 0; nj < 4; nj++)
#pragma unroll
            for (int hh = 0; hh < 2; hh++) {
                int row = wm * 64 + mi * 16 + (lane >> 2) + hh * 8;
                int col = n0 + wn * 32 + nj * 8 + 2 * (lane & 3);
                float2 v; v.x = acc[mi][nj][hh * 2]; v.y = acc[mi][nj][hh * 2 + 1];
                *(float2*)(O + (size_t)(r0 + row) * D_MODEL + col) = v;
            }
}

// ---------------- combine: out = Os + w0*Oe[s0] + w1*Oe[s1] -----------------------
__global__ void combine_kernel(float* __restrict__ out) {
    int t = blockIdx.x;
    int tid = threadIdx.x;
    int s0 = g_tok_slot[t * 2 + 0], s1 = g_tok_slot[t * 2 + 1];
    float w0 = g_tok_w[t * 2 + 0],  w1 = g_tok_w[t * 2 + 1];
    const float4* a = (const float4*)(g_Os + (size_t)t * D_MODEL) + tid;
    const float4* b = (const float4*)(g_Oe + (size_t)s0 * D_MODEL) + tid;
    const float4* c = (const float4*)(g_Oe + (size_t)s1 * D_MODEL) + tid;
    float4 va = *a, vb = *b, vc = *c;
    float4 r;
    r.x = va.x + w0 * vb.x + w1 * vc.x;
    r.y = va.y + w0 * vb.y + w1 * vc.y;
    r.z = va.z + w0 * vb.z + w1 * vc.z;
    r.w = va.w + w0 * vb.w + w1 * vc.w;
    *((float4*)(out + (size_t)t * D_MODEL) + tid) = r;
}

// ---------------- launch ------------------------------------------------------------
extern "C" void kernel_launch(void* const* d_in, const int* in_sizes, int n_in,
                              void* d_out, int out_size) {
    const float* x         = (const float*)d_in[0];
    const float* shared_wg = (const float*)d_in[1];
    const float* shared_wu = (const float*)d_in[2];
    const float* shared_wd = (const float*)d_in[3];
    const float* exp_wg    = (const float*)d_in[4];
    const float* exp_wu    = (const float*)d_in[5];
    const float* exp_wd    = (const float*)d_in[6];
    const float* router_w  = (const float*)d_in[7];
    float* out = (float*)d_out;

    __half *bgu, *bd;
    cudaGetSymbolAddress((void**)&bgu, g_Bgu);
    cudaGetSymbolAddress((void**)&bd, g_Bd);

    cudaFuncSetAttribute(mma_gateup_kernel,
                         cudaFuncAttributeMaxDynamicSharedMemorySize, MM_SMEM);
    cudaFuncSetAttribute(mma_down_kernel,
                         cudaFuncAttributeMaxDynamicSharedMemorySize, MM_SMEM);

    init_kernel<<<(MAXSLOT + 255) / 256, 256>>>();
    router_kernel<<<N_TOK / 4, 128>>>(x, router_w);
    offsets_kernel<<<1, 128>>>(out, out_size);
    scatter_kernel<<<N_TOK / 256, 256>>>();

    conv_x_kernel<<<(N_TOK * D_MODEL) / 512, 256>>>(x);
    conv_gu_kernel<<<dim3(D_FFN / 32, D_MODEL / 64, 9), 256>>>(
        shared_wg, exp_wg, shared_wu, exp_wu, bgu);
    conv_w_kernel<<<dim3(D_MODEL / 32, D_FFN / 64, 9), 256>>>(
        shared_wd, exp_wd, bd, D_FFN, D_MODEL);

    mma_gateup_kernel<<<dim3(D_FFN / 32, NT_SH + NT_DN), 128, MM_SMEM>>>();
    mma_down_kernel<<<dim3(D_MODEL / 64, NT_SH + NT_DN), 128, MM_SMEM>>>();
    combine_kernel<<<N_TOK, 256>>>(out);
}

// round 17
// speedup vs baseline: 1.1959x; 1.0147x over previous
#include <cuda_runtime.h>
#include <cuda_fp16.h>
#include <math.h>
#include <stdint.h>

#define D_MODEL 1024
#define D_FFN   2048
#define N_TOK   4096
#define N_EXP   8
#define MAXSLOT 9216
#define NT_SH   (N_TOK / 128)     /* 32 shared row tiles */
#define NT_DN   (MAXSLOT / 128)   /* 72 expert row tiles */

#define TILE_A  10240             /* 128 rows * 80B */
#define TILE_BB 5120              /* 64 rows * 80B  */
#define STG_B   (TILE_A + TILE_BB)/* 15360 */
#define MM_SMEM (3 * STG_B)       /* 46080, 3-stage ring, still 4 CTA/SM */
#define GU_NSTG 32                /* K=1024 / 32 */
#define DN_NSTG 64                /* K=2048 / 32 */

// ---------------- scratch ----------------------------------------------------
__device__ __half g_Xh[(size_t)N_TOK * D_MODEL];
// gate+up interleaved: [slab][4096 n][1024 k]; 64-chunk c: G cols [32c,32c+32)
// at +0..31, U cols [32c,32c+32) at +32..63
__device__ __half g_Bgu[(size_t)9 * 2 * D_FFN * D_MODEL];
__device__ __half g_Bd[(size_t)9 * D_MODEL * D_FFN];
__device__ __half g_Hs[(size_t)N_TOK * D_FFN];
__device__ __half g_He[(size_t)MAXSLOT * D_FFN];
__device__ float g_Os[(size_t)N_TOK * D_MODEL];
__device__ float g_Oe[(size_t)MAXSLOT * D_MODEL];
__device__ int   g_slot_token[MAXSLOT];
__device__ int   g_counts[N_EXP];
__device__ float g_psum[N_EXP];
__device__ int   g_fill[N_EXP];
__device__ int   g_padoff[N_EXP + 1];
__device__ int   g_tile_dn[NT_DN];
__device__ int   g_tok_idx[N_TOK * 2];
__device__ int   g_tok_slot[N_TOK * 2];
__device__ float g_tok_w[N_TOK * 2];

// ---------------- PTX helpers -------------------------------------------------
__device__ __forceinline__ uint32_t s2u(const void* p) {
    return (uint32_t)__cvta_generic_to_shared(p);
}
__device__ __forceinline__ void cpa16(uint32_t dst, const void* src) {
    asm volatile("cp.async.cg.shared.global [%0], [%1], 16;" :: "r"(dst), "l"(src));
}
__device__ __forceinline__ void cp_commit() {
    asm volatile("cp.async.commit_group;");
}
template <int N>
__device__ __forceinline__ void cp_wait() {
    asm volatile("cp.async.wait_group %0;" :: "n"(N));
}
__device__ __forceinline__ void ldm4(uint32_t* r, uint32_t addr) {
    asm volatile("ldmatrix.sync.aligned.m8n8.x4.shared.b16 {%0,%1,%2,%3}, [%4];"
                 : "=r"(r[0]), "=r"(r[1]), "=r"(r[2]), "=r"(r[3]) : "r"(addr));
}
__device__ __forceinline__ void mma_f16(float* c, const uint32_t* a,
                                        uint32_t b0, uint32_t b1) {
    asm volatile("mma.sync.aligned.m16n8k16.row.col.f32.f16.f16.f32 "
                 "{%0,%1,%2,%3}, {%4,%5,%6,%7}, {%8,%9}, {%0,%1,%2,%3};"
                 : "+f"(c[0]), "+f"(c[1]), "+f"(c[2]), "+f"(c[3])
                 : "r"(a[0]), "r"(a[1]), "r"(a[2]), "r"(a[3]), "r"(b0), "r"(b1));
}

// ---------------- routing kernels ---------------------------------------------
__global__ void init_kernel() {
    int i = blockIdx.x * blockDim.x + threadIdx.x;
    if (i < MAXSLOT) g_slot_token[i] = -1;
    if (i < N_EXP) { g_counts[i] = 0; g_psum[i] = 0.f; g_fill[i] = 0; }
}

__global__ void router_kernel(const float* __restrict__ x,
                              const float* __restrict__ rw) {
    int t = blockIdx.x * 4 + (threadIdx.x >> 5);
    int lane = threadIdx.x & 31;
    if (t >= N_TOK) return;
    const float* xr = x + (size_t)t * D_MODEL;
    float acc[N_EXP];
#pragma unroll
    for (int e = 0; e < N_EXP; e++) acc[e] = 0.f;
    for (int k = lane; k < D_MODEL; k += 32) {
        float xv = xr[k];
#pragma unroll
        for (int e = 0; e < N_EXP; e++) acc[e] += xv * rw[k * N_EXP + e];
    }
#pragma unroll
    for (int e = 0; e < N_EXP; e++)
#pragma unroll
        for (int o = 16; o; o >>= 1) acc[e] += __shfl_xor_sync(0xffffffffu, acc[e], o);
    if (lane == 0) {
        int i0 = 0; float v0 = acc[0];
#pragma unroll
        for (int e = 1; e < N_EXP; e++) if (acc[e] > v0) { v0 = acc[e]; i0 = e; }
        int i1 = -1; float v1 = -1e30f;
#pragma unroll
        for (int e = 0; e < N_EXP; e++) {
            if (e == i0) continue;
            if (acc[e] > v1) { v1 = acc[e]; i1 = e; }
        }
        float m2 = fmaxf(v0, v1);
        float e0 = expf(v0 - m2), e1 = expf(v1 - m2);
        float inv = 1.f / (e0 + e1);
        g_tok_idx[t * 2 + 0] = i0;  g_tok_w[t * 2 + 0] = e0 * inv;
        g_tok_idx[t * 2 + 1] = i1;  g_tok_w[t * 2 + 1] = e1 * inv;
        atomicAdd(&g_counts[i0], 1);
        atomicAdd(&g_counts[i1], 1);
        float mm = acc[0];
#pragma unroll
        for (int e = 1; e < N_EXP; e++) mm = fmaxf(mm, acc[e]);
        float s = 0.f, ex[N_EXP];
#pragma unroll
        for (int e = 0; e < N_EXP; e++) { ex[e] = expf(acc[e] - mm); s += ex[e]; }
        float invs = 1.f / s;
#pragma unroll
        for (int e = 0; e < N_EXP; e++) atomicAdd(&g_psum[e], ex[e] * invs);
    }
}

__global__ void offsets_kernel(float* __restrict__ out, int out_size) {
    __shared__ int spad[N_EXP + 1];
    int tid = threadIdx.x;
    if (tid == 0) {
        int off = 0;
        for (int e = 0; e < N_EXP; e++) {
            g_padoff[e] = off;
            off += ((g_counts[e] + 127) / 128) * 128;
        }
        g_padoff[N_EXP] = off;
        for (int e = 0; e <= N_EXP; e++) spad[e] = g_padoff[e];
        double s = 0.0;
        for (int e = 0; e < N_EXP; e++) s += (double)g_counts[e] * (double)g_psum[e];
        float aux = (float)((double)N_EXP * s / ((double)N_TOK * (double)N_TOK));
        if (out_size > N_TOK * D_MODEL) out[(size_t)N_TOK * D_MODEL] = aux;
    }
    __syncthreads();
    for (int j = tid; j < NT_DN; j += blockDim.x) {
        int row = j * 128, te = -1;
#pragma unroll
        for (int e = 0; e < N_EXP; e++)
            if (row >= spad[e] && row < spad[e + 1]) te = e;
        g_tile_dn[j] = te;
    }
}

__global__ void scatter_kernel() {
    int t = blockIdx.x * blockDim.x + threadIdx.x;
    if (t >= N_TOK) return;
#pragma unroll
    for (int k = 0; k < 2; k++) {
        int e = g_tok_idx[t * 2 + k];
        int pos = atomicAdd(&g_fill[e], 1);
        int slot = g_padoff[e] + pos;
        g_slot_token[slot] = t;
        g_tok_slot[t * 2 + k] = slot;
    }
}

// ---------------- conversions --------------------------------------------------
__global__ void conv_x_kernel(const float* __restrict__ x) {
    int i = (blockIdx.x * 256 + threadIdx.x) * 2;
    float2 v = *(const float2*)(x + i);
    __half2 h; h.x = __float2half(v.x); h.y = __float2half(v.y);
    *(__half2*)(g_Xh + i) = h;
}

// gate+up -> interleaved [slab][4096 n][1024 k] fp16, 64-row chunks (32G+32U)
__global__ void conv_gu_kernel(const float* __restrict__ srcGs, const float* __restrict__ srcGe,
                               const float* __restrict__ srcUs, const float* __restrict__ srcUe,
                               __half* __restrict__ o) {
    int slab = blockIdx.z;
    const float* G = (slab == 0) ? srcGs : srcGe + (size_t)(slab - 1) * D_MODEL * D_FFN;
    const float* U = (slab == 0) ? srcUs : srcUe + (size_t)(slab - 1) * D_MODEL * D_FFN;
    size_t ob = (size_t)slab * 2 * D_FFN * D_MODEL;
    __shared__ __half tg[64][34], tu[64][34];
    int tid = threadIdx.x;
    int tx = tid & 31, ty = tid >> 5;
    int k0 = blockIdx.y * 64, j0 = blockIdx.x * 32;
#pragma unroll
    for (int p = 0; p < 8; p++) {
        int row = p * 8 + ty;
        size_t so = (size_t)(k0 + row) * D_FFN + j0 + tx;
        tg[row][tx] = __float2half(G[so]);
        tu[row][tx] = __float2half(U[so]);
    }
    __syncthreads();
    int nG0 = 2 * j0;                  // 64-chunk interleave: G at +0..31, U at +32..63
    int pk = tx;
#pragma unroll
    for (int pass = 0; pass < 4; pass++) {
        int jj = pass * 8 + ty;
        __half2 vg; vg.x = tg[2 * pk][jj]; vg.y = tg[2 * pk + 1][jj];
        __half2 vu; vu.x = tu[2 * pk][jj]; vu.y = tu[2 * pk + 1][jj];
        *(__half2*)(o + ob + (size_t)(nG0 + jj) * D_MODEL + k0 + 2 * pk) = vg;
        *(__half2*)(o + ob + (size_t)(nG0 + 32 + jj) * D_MODEL + k0 + 2 * pk) = vu;
    }
}

// down: transpose [R,C] fp32 -> [slab][C][R] fp16
__global__ void conv_w_kernel(const float* __restrict__ srcS, const float* __restrict__ srcE,
                              __half* __restrict__ o, int R, int C) {
    int slab = blockIdx.z;
    const float* src = (slab == 0) ? srcS : srcE + (size_t)(slab - 1) * R * C;
    size_t ob = (size_t)slab * R * C;
    __shared__ __half t[64][34];
    int tid = threadIdx.x;
    int tx = tid & 31, ty = tid >> 5;
    int r0 = blockIdx.y * 64, c0 = blockIdx.x * 32;
#pragma unroll
    for (int p = 0; p < 8; p++) {
        int row = p * 8 + ty;
        t[row][tx] = __float2half(src[(size_t)(r0 + row) * C + c0 + tx]);
    }
    __syncthreads();
    int pk = tx;
#pragma unroll
    for (int pass = 0; pass < 4; pass++) {
        int jj = pass * 8 + ty;
        __half2 v; v.x = t[2 * pk][jj]; v.y = t[2 * pk + 1][jj];
        *(__half2*)(o + ob + (size_t)(c0 + jj) * R + r0 + 2 * pk) = v;
    }
}

// ---------------- gate+up GEMM: 128M x 64N(=32G+32U), 128 thr, 4 CTA/SM ---------
__global__ void __launch_bounds__(128, 4) mma_gateup_kernel() {
    const int by = blockIdx.y;
    const bool sh = (by < NT_SH);
    int te = 0, r0;
    if (sh) r0 = by * 128;
    else {
        int be = by - NT_SH;
        te = g_tile_dn[be];
        if (te < 0) return;
        r0 = be * 128;
    }
    const int slab = sh ? 0 : 1 + te;
    const int n0b = blockIdx.x * 64;         // interleaved B row base
    const int h0 = blockIdx.x * 32;          // H column base
    const int tid = threadIdx.x, lane = tid & 31, wid = tid >> 5;
    const int wm = wid & 1, wn = wid >> 1;   // wn: 0 = G warps, 1 = U warps

    extern __shared__ __align__(16) char smem[];
    __shared__ int stok[128];
    const uint32_t sbase = s2u(smem);

    if (sh) stok[tid] = r0 + tid;
    else { int t = g_slot_token[r0 + tid]; stok[tid] = t < 0 ? 0 : t; }
    __syncthreads();

    const __half* __restrict__ B = g_Bgu + (size_t)slab * 2 * D_FFN * D_MODEL;

    auto load_stage = [&](int s) {
        const int k0 = s << 5;
        const uint32_t st = sbase + (s % 3) * STG_B;
#pragma unroll
        for (int it = 0; it < 4; it++) {         // A: 512 cpa16
            int idx = tid + it * 128;
            int row = idx >> 2, ch = idx & 3;
            cpa16(st + row * 80 + ch * 16,
                  g_Xh + (size_t)stok[row] * D_MODEL + k0 + ch * 8);
        }
#pragma unroll
        for (int it = 0; it < 2; it++) {         // B: 256 cpa16
            int idx = tid + it * 128;
            int row = idx >> 2, ch = idx & 3;
            cpa16(st + TILE_A + row * 80 + ch * 16,
                  B + (size_t)(n0b + row) * D_MODEL + k0 + ch * 8);
        }
        cp_commit();
    };

    float acc[4][4][4];
#pragma unroll
    for (int i = 0; i < 4; i++)
#pragma unroll
        for (int j = 0; j < 4; j++)
#pragma unroll
            for (int q = 0; q < 4; q++) acc[i][j][q] = 0.f;

    load_stage(0); load_stage(1);
    for (int s = 0; s < GU_NSTG; s++) {
        cp_wait<1>();
        __syncthreads();
        if (s + 2 < GU_NSTG) load_stage(s + 2); else cp_commit();
        const uint32_t st = sbase + (s % 3) * STG_B;
        const int lr = lane & 15, lc = (lane >> 4) * 16;
#pragma unroll
        for (int kh = 0; kh < 2; kh++) {
            const int kb = kh * 32 + lc;
            uint32_t a[4][4];
#pragma unroll
            for (int mi = 0; mi < 4; mi++)
                ldm4(a[mi], st + (wm * 64 + mi * 16 + lr) * 80 + kb);
#pragma unroll
            for (int nj2 = 0; nj2 < 2; nj2++) {
                uint32_t bf[4];
                ldm4(bf, st + TILE_A + (wn * 32 + nj2 * 16 + lr) * 80 + kb);
#pragma unroll
                for (int mi = 0; mi < 4; mi++) {
                    mma_f16(acc[mi][nj2 * 2],     a[mi], bf[0], bf[2]);
                    mma_f16(acc[mi][nj2 * 2 + 1], a[mi], bf[1], bf[3]);
                }
            }
        }
    }

    // SwiGLU epilogue: G warps (wn=0) -> gbuf fp32; U warps compute H -> hbuf;
    // then all threads store coalesced.
    __syncthreads();
    float* gbuf = (float*)smem;                 // [128][34] fp32 = 17408 B
    __half* hbuf = (__half*)(smem + 17408);     // [128][40] half = 10240 B
    if (wn == 0) {
#pragma unroll
        for (int mi = 0; mi < 4; mi++)
#pragma unroll
            for (int nj = 0; nj < 4; nj++)
#pragma unroll
                for (int hh = 0; hh < 2; hh++) {
                    int row = wm * 64 + mi * 16 + (lane >> 2) + hh * 8;
                    int col = nj * 8 + 2 * (lane & 3);
                    float2 v; v.x = acc[mi][nj][hh * 2]; v.y = acc[mi][nj][hh * 2 + 1];
                    *(float2*)(gbuf + row * 34 + col) = v;
                }
    }
    __syncthreads();
    if (wn == 1) {
#pragma unroll
        for (int mi = 0; mi < 4; mi++)
#pragma unroll
            for (int nj = 0; nj < 4; nj++)
#pragma unroll
                for (int hh = 0; hh < 2; hh++) {
                    int row = wm * 64 + mi * 16 + (lane >> 2) + hh * 8;
                    int col = nj * 8 + 2 * (lane & 3);
                    float2 g2 = *(const float2*)(gbuf + row * 34 + col);
                    float u0 = acc[mi][nj][hh * 2], u1 = acc[mi][nj][hh * 2 + 1];
                    float h0v = g2.x / (1.f + expf(-g2.x)) * u0;
                    float h1v = g2.y / (1.f + expf(-g2.y)) * u1;
                    __half2 hv;
                    hv.x = __float2half(h0v);
                    hv.y = __float2half(h1v);
                    *(__half2*)(hbuf + row * 40 + col) = hv;
                }
    }
    __syncthreads();
    {
        __half* __restrict__ H = sh ? g_Hs : g_He;
#pragma unroll
        for (int it = 0; it < 4; it++) {
            int idx = tid + it * 128;
            int row = idx >> 2, q = idx & 3;
            uint4 v = *(const uint4*)(hbuf + row * 40 + q * 8);
            *(uint4*)(H + (size_t)(r0 + row) * D_FFN + h0 + q * 8) = v;
        }
    }
}

// ---------------- down GEMM: 128M x 64N, 128 thr, 4 CTA/SM -----------------------
__global__ void __launch_bounds__(128, 4) mma_down_kernel() {
    const int by = blockIdx.y;
    const bool sh = (by < NT_SH);
    int te = 0, r0;
    if (sh) r0 = by * 128;
    else {
        int be = by - NT_SH;
        te = g_tile_dn[be];
        if (te < 0) return;
        r0 = be * 128;
    }
    const int slab = sh ? 0 : 1 + te;
    const int n0 = blockIdx.x * 64;
    const int tid = threadIdx.x, lane = tid & 31, wid = tid >> 5;
    const int wm = wid & 1, wn = wid >> 1;

    extern __shared__ __align__(16) char smem[];
    const uint32_t sbase = s2u(smem);

    const __half* __restrict__ Ah = sh ? g_Hs : g_He;
    const __half* __restrict__ B = g_Bd + (size_t)slab * D_MODEL * D_FFN;

    auto load_stage = [&](int s) {
        const int k0 = s << 5;
        const uint32_t st = sbase + (s % 3) * STG_B;
#pragma unroll
        for (int it = 0; it < 4; it++) {
            int idx = tid + it * 128;
            int row = idx >> 2, ch = idx & 3;
            cpa16(st + row * 80 + ch * 16,
                  Ah + (size_t)(r0 + row) * D_FFN + k0 + ch * 8);
        }
#pragma unroll
        for (int it = 0; it < 2; it++) {
            int idx = tid + it * 128;
            int row = idx >> 2, ch = idx & 3;
            cpa16(st + TILE_A + row * 80 + ch * 16,
                  B + (size_t)(n0 + row) * D_FFN + k0 + ch * 8);
        }
        cp_commit();
    };

    float acc[4][4][4];
#pragma unroll
    for (int i = 0; i < 4; i++)
#pragma unroll
        for (int j = 0; j < 4; j++)
#pragma unroll
            for (int q = 0; q < 4; q++) acc[i][j][q] = 0.f;

    load_stage(0); load_stage(1);
    for (int s = 0; s < DN_NSTG; s++) {
        cp_wait<1>();
        __syncthreads();
        if (s + 2 < DN_NSTG) load_stage(s + 2); else cp_commit();
        const uint32_t st = sbase + (s % 3) * STG_B;
        const int lr = lane & 15, lc = (lane >> 4) * 16;
#pragma unroll
        for (int kh = 0; kh < 2; kh++) {
            const int kb = kh * 32 + lc;
            uint32_t a[4][4];
#pragma unroll
            for (int mi = 0; mi < 4; mi++)
                ldm4(a[mi], st + (wm * 64 + mi * 16 + lr) * 80 + kb);
#pragma unroll
            for (int nj2 = 0; nj2 < 2; nj2++) {
                uint32_t bf[4];
                ldm4(bf, st + TILE_A + (wn * 32 + nj2 * 16 + lr) * 80 + kb);
#pragma unroll
                for (int mi = 0; mi < 4; mi++) {
                    mma_f16(acc[mi][nj2 * 2],     a[mi], bf[0], bf[2]);
                    mma_f16(acc[mi][nj2 * 2 + 1], a[mi], bf[1], bf[3]);
                }
            }
        }
    }

    float* __restrict__ O = sh ? g_Os : g_Oe;
#pragma unroll
    for (int mi = 0; mi < 4; mi++)
#pragma unroll
        for (int nj = 0; nj < 4; nj++)
#pragma unroll
            for (int hh = 0; hh < 2; hh++) {
                int row = wm * 64 + mi * 16 + (lane >> 2) + hh * 8;
                int col = n0 + wn * 32 + nj * 8 + 2 * (lane & 3);
                float2 v; v.x = acc[mi][nj][hh * 2]; v.y = acc[mi][nj][hh * 2 + 1];
                *(float2*)(O + (size_t)(r0 + row) * D_MODEL + col) = v;
            }
}

// ---------------- combine: out = Os + w0*Oe[s0] + w1*Oe[s1] -----------------------
__global__ void combine_kernel(float* __restrict__ out) {
    int t = blockIdx.x;
    int tid = threadIdx.x;
    int s0 = g_tok_slot[t * 2 + 0], s1 = g_tok_slot[t * 2 + 1];
    float w0 = g_tok_w[t * 2 + 0],  w1 = g_tok_w[t * 2 + 1];
    const float4* a = (const float4*)(g_Os + (size_t)t * D_MODEL) + tid;
    const float4* b = (const float4*)(g_Oe + (size_t)s0 * D_MODEL) + tid;
    const float4* c = (const float4*)(g_Oe + (size_t)s1 * D_MODEL) + tid;
    float4 va = *a, vb = *b, vc = *c;
    float4 r;
    r.x = va.x + w0 * vb.x + w1 * vc.x;
    r.y = va.y + w0 * vb.y + w1 * vc.y;
    r.z = va.z + w0 * vb.z + w1 * vc.z;
    r.w = va.w + w0 * vb.w + w1 * vc.w;
    *((float4*)(out + (size_t)t * D_MODEL) + tid) = r;
}

// ---------------- launch ------------------------------------------------------------
extern "C" void kernel_launch(void* const* d_in, const int* in_sizes, int n_in,
                              void* d_out, int out_size) {
    const float* x         = (const float*)d_in[0];
    const float* shared_wg = (const float*)d_in[1];
    const float* shared_wu = (const float*)d_in[2];
    const float* shared_wd = (const float*)d_in[3];
    const float* exp_wg    = (const float*)d_in[4];
    const float* exp_wu    = (const float*)d_in[5];
    const float* exp_wd    = (const float*)d_in[6];
    const float* router_w  = (const float*)d_in[7];
    float* out = (float*)d_out;

    __half *bgu, *bd;
    cudaGetSymbolAddress((void**)&bgu, g_Bgu);
    cudaGetSymbolAddress((void**)&bd, g_Bd);

    cudaFuncSetAttribute(mma_gateup_kernel,
                         cudaFuncAttributeMaxDynamicSharedMemorySize, MM_SMEM);
    cudaFuncSetAttribute(mma_down_kernel,
                         cudaFuncAttributeMaxDynamicSharedMemorySize, MM_SMEM);

    init_kernel<<<(MAXSLOT + 255) / 256, 256>>>();
    router_kernel<<<N_TOK / 4, 128>>>(x, router_w);
    offsets_kernel<<<1, 128>>>(out, out_size);
    scatter_kernel<<<N_TOK / 256, 256>>>();

    conv_x_kernel<<<(N_TOK * D_MODEL) / 512, 256>>>(x);
    conv_gu_kernel<<<dim3(D_FFN / 32, D_MODEL / 64, 9), 256>>>(
        shared_wg, exp_wg, shared_wu, exp_wu, bgu);
    conv_w_kernel<<<dim3(D_MODEL / 32, D_FFN / 64, 9), 256>>>(
        shared_wd, exp_wd, bd, D_FFN, D_MODEL);

    mma_gateup_kernel<<<dim3(D_FFN / 32, NT_SH + NT_DN), 128, MM_SMEM>>>();
    mma_down_kernel<<<dim3(D_MODEL / 64, NT_SH + NT_DN), 128, MM_SMEM>>>();
    combine_kernel<<<N_TOK, 256>>>(out);
}